// round 12
// baseline (speedup 1.0000x reference)
#include <cuda_runtime.h>
#include <cuda_fp16.h>
#include <math.h>
#include <stdint.h>

// Problem constants
#define BATCH 4
#define SEQ   512
#define DMODEL 768
#define FFDIM 3072
#define NHEAD 12
#define HDIM  64
#define NTOK  (BATCH*SEQ)          // 2048
#define NBLOCKS 12

// ---------------- scratch (device globals; no allocation allowed) -----------
__device__ __half g_xln[NTOK * DMODEL];
__device__ __half g_q  [NTOK * DMODEL];
__device__ __half g_k  [NTOK * DMODEL];
__device__ __half g_vt [NTOK * DMODEL];   // per (b,h): [64 dims][512 tokens]
__device__ __half g_h1 [NTOK * FFDIM];
// fp16, TRANSPOSED weights: wt[n][k] = half(W[k][n])
__device__ __half g_wqT[DMODEL * DMODEL];
__device__ __half g_wkT[DMODEL * DMODEL];
__device__ __half g_wvT[DMODEL * DMODEL];
__device__ __half g_w0T[FFDIM * DMODEL];
__device__ __half g_w1T[DMODEL * FFDIM];

__device__ __forceinline__ void cpa16(unsigned dst, const void* src) {
    asm volatile("cp.async.cg.shared.global [%0], [%1], 16;\n" :: "r"(dst), "l"(src));
}
__device__ __forceinline__ void cpa_commit() {
    asm volatile("cp.async.commit_group;\n" ::: "memory");
}
template <int N>
__device__ __forceinline__ void cpa_wait() {
    asm volatile("cp.async.wait_group %0;\n" :: "n"(N) : "memory");
}
__device__ __forceinline__ unsigned smem_u32(const void* p) {
    unsigned r;
    asm("{ .reg .u64 t; cvta.to.shared.u64 t, %1; cvt.u32.u64 %0, t; }"
        : "=r"(r) : "l"(p));
    return r;
}
__device__ __forceinline__ unsigned packh2(float a, float b) {
    __half2 h = __floats2half2_rn(a, b);
    return *(unsigned*)&h;
}
__device__ __forceinline__ void ldsm_x4(unsigned& r0, unsigned& r1,
                                        unsigned& r2, unsigned& r3, unsigned addr) {
    asm volatile("ldmatrix.sync.aligned.m8n8.x4.shared.b16 {%0,%1,%2,%3}, [%4];"
        : "=r"(r0), "=r"(r1), "=r"(r2), "=r"(r3) : "r"(addr));
}

#define HMMA16816(acc, a0, a1, a2, a3, b0, b1) \
    asm volatile( \
        "mma.sync.aligned.m16n8k16.row.col.f32.f16.f16.f32 " \
        "{%0,%1,%2,%3}, {%4,%5,%6,%7}, {%8,%9}, {%0,%1,%2,%3};" \
        : "+f"((acc)[0]), "+f"((acc)[1]), "+f"((acc)[2]), "+f"((acc)[3]) \
        : "r"(a0), "r"(a1), "r"(a2), "r"(a3), "r"(b0), "r"(b1))

// ---------------- transpose + fp16 convert (weights, once per launch) -------
__global__ __launch_bounds__(256) void transpose_h_kernel(
    const float* __restrict__ src, __half* __restrict__ dst, int R, int C)
{
    __shared__ float t[32][33];
    const int c0 = blockIdx.x * 32, r0 = blockIdx.y * 32;
    const int tx = threadIdx.x, ty = threadIdx.y;
#pragma unroll
    for (int i = 0; i < 4; i++)
        t[ty + 8 * i][tx] = src[(size_t)(r0 + ty + 8 * i) * C + c0 + tx];
    __syncthreads();
#pragma unroll
    for (int i = 0; i < 4; i++)
        dst[(size_t)(c0 + ty + 8 * i) * R + r0 + tx] = __float2half_rn(t[tx][ty + 8 * i]);
}

// ---------------- LayerNorm: warp per row; outputs fp16 ---------------------
__global__ __launch_bounds__(256) void ln_kernel(
    const float* __restrict__ x, const float* __restrict__ g,
    const float* __restrict__ be, __half* __restrict__ y)
{
    const int wid = threadIdx.x >> 5, lane = threadIdx.x & 31;
    const int r = blockIdx.x * 8 + wid;
    const float* xr = x + (size_t)r * DMODEL;

    float4 v[6];
    float s = 0.f, s2 = 0.f;
#pragma unroll
    for (int i = 0; i < 6; i++) {
        v[i] = *(const float4*)(xr + (i * 32 + lane) * 4);
        s  += v[i].x + v[i].y + v[i].z + v[i].w;
        s2 += v[i].x * v[i].x + v[i].y * v[i].y + v[i].z * v[i].z + v[i].w * v[i].w;
    }
#pragma unroll
    for (int o = 16; o > 0; o >>= 1) {
        s  += __shfl_xor_sync(0xffffffffu, s,  o);
        s2 += __shfl_xor_sync(0xffffffffu, s2, o);
    }
    const float mu  = s  * (1.f / DMODEL);
    const float var = s2 * (1.f / DMODEL) - mu * mu;
    const float inv = rsqrtf(var + 1e-5f);
    __half* yr = y + (size_t)r * DMODEL;
#pragma unroll
    for (int i = 0; i < 6; i++) {
        const int col = (i * 32 + lane) * 4;
        float4 gg = *(const float4*)(g + col);
        float4 bb = *(const float4*)(be + col);
        unsigned p0 = packh2((v[i].x - mu) * inv * gg.x + bb.x,
                             (v[i].y - mu) * inv * gg.y + bb.y);
        unsigned p1 = packh2((v[i].z - mu) * inv * gg.z + bb.z,
                             (v[i].w - mu) * inv * gg.w + bb.w);
        uint2 o; o.x = p0; o.y = p1;
        *(uint2*)(yr + col) = o;
    }
}

// ===================== FP16 tensor-core GEMM ================================
// Single barrier per K chunk (3-stage pipeline makes the trailing sync
// provably redundant: issue(c+2) writes stage (c-1)%3, whose readers all
// passed this chunk's top barrier).
#define BKH 64
#define NSTAGE 3

template <int MT, int MODE>
__device__ __forceinline__ void h_gemm_core(
    const __half* __restrict__ A, const __half* __restrict__ BT,
    const float* __restrict__ bias, void* __restrict__ Cv,
    int N, int K)
{
    constexpr int BMv  = MT * 32;
    constexpr int ASTG = BMv * 32;
    constexpr int BSTG = 128 * 32;

    extern __shared__ unsigned smemU[];
    unsigned* As = smemU;
    unsigned* Bs = smemU + NSTAGE * ASTG;
    const unsigned asBase = smem_u32(As);
    const unsigned bsBase = smem_u32(Bs);

    const int tid  = threadIdx.x;
    const int lane = tid & 31;
    const int wid  = tid >> 5;
    const int wm   = wid >> 2;
    const int wn   = wid & 3;
    const int rowBase = blockIdx.y * BMv;
    const int colBase = blockIdx.x * 128;
    const int lq = lane >> 2;
    const int lr = lane & 3;

    const int aRowOff = ((lane >> 3) & 1) * 8 + (lane & 7);
    const int aKhalf  = lane >> 4;
    const int bRowOff = ((lane >> 4) & 1) * 8 + (lane & 7);
    const int bKhalf  = (lane >> 3) & 1;

    auto issue = [&](int c) {
        const int st = c % NSTAGE;
        const int k0 = c * BKH;
#pragma unroll
        for (int i = 0; i < MT; i++) {
            int fi = tid + i * 256;
            int r = fi >> 3, c8 = fi & 7;
            unsigned u = (unsigned)(c8 * 4) ^ (((unsigned)r & 7u) << 2);
            cpa16(asBase + (st * ASTG + r * 32 + u) * 4u,
                  A + (size_t)(rowBase + r) * K + k0 + c8 * 8);
        }
#pragma unroll
        for (int i = 0; i < 4; i++) {
            int fi = tid + i * 256;
            int r = fi >> 3, c8 = fi & 7;
            unsigned u = (unsigned)(c8 * 4) ^ (((unsigned)r & 7u) << 2);
            cpa16(bsBase + (st * BSTG + r * 32 + u) * 4u,
                  BT + (size_t)(colBase + r) * K + k0 + c8 * 8);
        }
    };

    float acc[MT][4][4];
#pragma unroll
    for (int i = 0; i < MT; i++)
#pragma unroll
        for (int j = 0; j < 4; j++)
#pragma unroll
            for (int t = 0; t < 4; t++) acc[i][j][t] = 0.f;

    const int nch = K / BKH;
    issue(0); cpa_commit();
    issue(1); cpa_commit();

    for (int c = 0; c < nch; c++) {
        cpa_wait<1>();
        __syncthreads();
        if (c + 2 < nch) issue(c + 2);
        cpa_commit();

        const unsigned stA = asBase + (unsigned)((c % NSTAGE) * ASTG) * 4u;
        const unsigned stB = bsBase + (unsigned)((c % NSTAGE) * BSTG) * 4u;
#pragma unroll
        for (int ks = 0; ks < 4; ks++) {
            unsigned af[MT][4];
#pragma unroll
            for (int mt = 0; mt < MT; mt++) {
                int r = wm * (MT * 16) + mt * 16 + aRowOff;
                int c2 = ks * 2 + aKhalf;
                unsigned off = (unsigned)(r * 32) + (((unsigned)(c2 * 4)) ^ (((unsigned)r & 7u) << 2));
                ldsm_x4(af[mt][0], af[mt][1], af[mt][2], af[mt][3], stA + off * 4u);
            }
            unsigned bf[4][2];
#pragma unroll
            for (int ntp = 0; ntp < 2; ntp++) {
                int nrow = wn * 32 + ntp * 16 + bRowOff;
                int c2 = ks * 2 + bKhalf;
                unsigned off = (unsigned)(nrow * 32) + (((unsigned)(c2 * 4)) ^ (((unsigned)nrow & 7u) << 2));
                ldsm_x4(bf[2 * ntp][0], bf[2 * ntp][1],
                        bf[2 * ntp + 1][0], bf[2 * ntp + 1][1], stB + off * 4u);
            }
#pragma unroll
            for (int nt = 0; nt < 4; nt++)
#pragma unroll
                for (int mt = 0; mt < MT; mt++)
                    HMMA16816(acc[mt][nt], af[mt][0], af[mt][1], af[mt][2], af[mt][3],
                              bf[nt][0], bf[nt][1]);
        }
        // (no trailing __syncthreads: 3-stage pipeline guarantees safety)
    }

#pragma unroll
    for (int mt = 0; mt < MT; mt++) {
        int row = rowBase + wm * (MT * 16) + mt * 16 + lq;
#pragma unroll
        for (int nt = 0; nt < 4; nt++) {
            int col = colBase + wn * 32 + nt * 8 + lr * 2;
            float b0 = bias[col], b1 = bias[col + 1];
            float v00 = acc[mt][nt][0] + b0;
            float v01 = acc[mt][nt][1] + b1;
            float v10 = acc[mt][nt][2] + b0;
            float v11 = acc[mt][nt][3] + b1;
            if (MODE == 1) {
                v00 = 0.5f * v00 * (1.0f + erff(v00 * 0.70710678118654752f));
                v01 = 0.5f * v01 * (1.0f + erff(v01 * 0.70710678118654752f));
                v10 = 0.5f * v10 * (1.0f + erff(v10 * 0.70710678118654752f));
                v11 = 0.5f * v11 * (1.0f + erff(v11 * 0.70710678118654752f));
            }
            if (MODE == 0 || MODE == 1) {
                __half* C = (__half*)Cv;
                *(unsigned*)(C + (size_t)row * N + col)       = packh2(v00, v01);
                *(unsigned*)(C + (size_t)(row + 8) * N + col) = packh2(v10, v11);
            } else if (MODE == 2) {
                float* C = (float*)Cv;
                float2 c0 = *(const float2*)(C + (size_t)row * N + col);
                float2 c1 = *(const float2*)(C + (size_t)(row + 8) * N + col);
                c0.x += v00; c0.y += v01;
                c1.x += v10; c1.y += v11;
                *(float2*)(C + (size_t)row * N + col) = c0;
                *(float2*)(C + (size_t)(row + 8) * N + col) = c1;
            } else {  // MODE 4: V transposed store -> vt[(b*DMODEL+col)*SEQ + tok]
                __half* C = (__half*)Cv;
                int bb = row >> 9;
                int tok = row & 511;
                size_t base = ((size_t)(bb * DMODEL + col)) * SEQ;
                C[base + tok]           = __float2half_rn(v00);
                C[base + SEQ + tok]     = __float2half_rn(v01);
                C[base + tok + 8]       = __float2half_rn(v10);
                C[base + SEQ + tok + 8] = __float2half_rn(v11);
            }
        }
    }
}

template <int MT, int MODE>
__global__ __launch_bounds__(256) void h_gemm_kernel(
    const __half* __restrict__ A, const __half* __restrict__ BT,
    const float* __restrict__ bias, void* __restrict__ C, int N, int K)
{
    h_gemm_core<MT, MODE>(A, BT, bias, C, N, K);
}

__global__ __launch_bounds__(256) void h_gemm_qkv_kernel(
    const __half* __restrict__ A,
    const __half* __restrict__ WqT, const __half* __restrict__ WkT,
    const __half* __restrict__ WvT,
    const float* __restrict__ bq, const float* __restrict__ bk,
    const float* __restrict__ bv,
    __half* __restrict__ q, __half* __restrict__ k, __half* __restrict__ vt)
{
    if (blockIdx.z == 0)      h_gemm_core<4, 0>(A, WqT, bq, (void*)q,  DMODEL, DMODEL);
    else if (blockIdx.z == 1) h_gemm_core<4, 0>(A, WkT, bk, (void*)k,  DMODEL, DMODEL);
    else                      h_gemm_core<4, 4>(A, WvT, bv, (void*)vt, DMODEL, DMODEL);
}

#define HGEMM_SMEM_128 (NSTAGE * (128*32 + 128*32) * 4)   // 98304
#define HGEMM_SMEM_64  (NSTAGE * (64*32  + 128*32) * 4)   // 73728

// ===================== Flash attention (fp16 mma, online softmax) ===========
// ldmatrix fragment loads; Q fragments hoisted into registers (loaded once).
#define FA_SMEM_BYTES ((4096 + 2*2048 + 2*2048) * 4)   // 49152

__global__ __launch_bounds__(256) void fattn_kernel(
    const __half* __restrict__ q, const __half* __restrict__ k,
    const __half* __restrict__ vt, float* __restrict__ x)
{
    extern __shared__ unsigned sm[];
    unsigned* Qs = sm;                 // [128][32]
    const unsigned qsB = smem_u32(Qs);
    const unsigned ksB = qsB + 4096 * 4u;   // [2][64][32]
    const unsigned vsB = qsB + 8192 * 4u;   // [2][64][32]

    const int tid = threadIdx.x;
    const int lane = tid & 31;
    const int wid = tid >> 5;
    const int lq = lane >> 2;
    const int lr = lane & 3;

    const int aRowOff = ((lane >> 3) & 1) * 8 + (lane & 7);
    const int aKhalf  = lane >> 4;
    const int bRowOff = ((lane >> 4) & 1) * 8 + (lane & 7);
    const int bKhalf  = (lane >> 3) & 1;

    const int qt = blockIdx.x;
    const int bh = blockIdx.y;
    const int b = bh / NHEAD, h = bh % NHEAD;

    const __half* qb  = q  + ((size_t)b * SEQ + qt * 128) * DMODEL + h * HDIM;
    const __half* kb  = k  + (size_t)b * SEQ * DMODEL + h * HDIM;
    const __half* vtb = vt + (size_t)bh * HDIM * SEQ;

    auto issueQ = [&]() {
#pragma unroll
        for (int i = 0; i < 4; i++) {
            int fi = tid + i * 256;
            int r = fi >> 3, c8 = fi & 7;
            unsigned u = (unsigned)(c8 * 4) ^ (((unsigned)r & 7u) << 2);
            cpa16(qsB + (r * 32 + u) * 4u, qb + (size_t)r * DMODEL + c8 * 8);
        }
    };
    auto issueK = [&](int kt) {
#pragma unroll
        for (int i = 0; i < 2; i++) {
            int fi = tid + i * 256;
            int r = fi >> 3, c8 = fi & 7;
            unsigned u = (unsigned)(c8 * 4) ^ (((unsigned)r & 7u) << 2);
            cpa16(ksB + ((kt & 1) * 2048 + r * 32 + u) * 4u,
                  kb + (size_t)(kt * 64 + r) * DMODEL + c8 * 8);
        }
    };
    auto issueV = [&](int kt) {
#pragma unroll
        for (int i = 0; i < 2; i++) {
            int fi = tid + i * 256;
            int r = fi >> 3, c8 = fi & 7;
            unsigned u = (unsigned)(c8 * 4) ^ (((unsigned)r & 7u) << 2);
            cpa16(vsB + ((kt & 1) * 2048 + r * 32 + u) * 4u,
                  vtb + (size_t)r * SEQ + kt * 64 + c8 * 8);
        }
    };

    issueQ(); issueK(0); issueV(0); cpa_commit();
    issueK(1); issueV(1); cpa_commit();

    float oacc[8][4];
#pragma unroll
    for (int nt = 0; nt < 8; nt++)
#pragma unroll
        for (int t = 0; t < 4; t++) oacc[nt][t] = 0.f;
    float mRun0 = -1e30f, mRun1 = -1e30f;
    float lRun0 = 0.f, lRun1 = 0.f;

    const int r0 = wid * 16 + lq;
    unsigned qf[4][4];   // Q fragments, loaded once at kt==0

    for (int kt = 0; kt < 8; kt++) {
        cpa_wait<1>();
        __syncthreads();

        if (kt == 0) {
#pragma unroll
            for (int ks = 0; ks < 4; ks++) {
                int r = wid * 16 + aRowOff;
                int c2 = ks * 2 + aKhalf;
                unsigned off = (unsigned)(r * 32) +
                               (((unsigned)(c2 * 4)) ^ (((unsigned)r & 7u) << 2));
                ldsm_x4(qf[ks][0], qf[ks][1], qf[ks][2], qf[ks][3], qsB + off * 4u);
            }
        }

        float sacc[8][4];
#pragma unroll
        for (int nt = 0; nt < 8; nt++)
#pragma unroll
            for (int t = 0; t < 4; t++) sacc[nt][t] = 0.f;

        const unsigned stK = ksB + (unsigned)((kt & 1) * 2048) * 4u;
        const unsigned stV = vsB + (unsigned)((kt & 1) * 2048) * 4u;
#pragma unroll
        for (int ks = 0; ks < 4; ks++) {
            unsigned kf[8][2];
#pragma unroll
            for (int ntp = 0; ntp < 4; ntp++) {
                int nrow = ntp * 16 + bRowOff;
                int c2 = ks * 2 + bKhalf;
                unsigned off = (unsigned)(nrow * 32) +
                               (((unsigned)(c2 * 4)) ^ (((unsigned)nrow & 7u) << 2));
                ldsm_x4(kf[2 * ntp][0], kf[2 * ntp][1],
                        kf[2 * ntp + 1][0], kf[2 * ntp + 1][1], stK + off * 4u);
            }
#pragma unroll
            for (int nt = 0; nt < 8; nt++)
                HMMA16816(sacc[nt], qf[ks][0], qf[ks][1], qf[ks][2], qf[ks][3],
                          kf[nt][0], kf[nt][1]);
        }

        float m0 = -1e30f, m1 = -1e30f;
#pragma unroll
        for (int nt = 0; nt < 8; nt++) {
            sacc[nt][0] *= 0.125f; sacc[nt][1] *= 0.125f;
            sacc[nt][2] *= 0.125f; sacc[nt][3] *= 0.125f;
            m0 = fmaxf(m0, fmaxf(sacc[nt][0], sacc[nt][1]));
            m1 = fmaxf(m1, fmaxf(sacc[nt][2], sacc[nt][3]));
        }
#pragma unroll
        for (int o = 1; o <= 2; o <<= 1) {
            m0 = fmaxf(m0, __shfl_xor_sync(0xffffffffu, m0, o));
            m1 = fmaxf(m1, __shfl_xor_sync(0xffffffffu, m1, o));
        }
        const float nm0 = fmaxf(mRun0, m0);
        const float nm1 = fmaxf(mRun1, m1);
        const float sc0 = __expf(mRun0 - nm0);
        const float sc1 = __expf(mRun1 - nm1);
        mRun0 = nm0; mRun1 = nm1;

        float lt0 = 0.f, lt1 = 0.f;
#pragma unroll
        for (int nt = 0; nt < 8; nt++) {
            sacc[nt][0] = __expf(sacc[nt][0] - nm0);
            sacc[nt][1] = __expf(sacc[nt][1] - nm0);
            sacc[nt][2] = __expf(sacc[nt][2] - nm1);
            sacc[nt][3] = __expf(sacc[nt][3] - nm1);
            lt0 += sacc[nt][0] + sacc[nt][1];
            lt1 += sacc[nt][2] + sacc[nt][3];
        }
        lRun0 = lRun0 * sc0 + lt0;
        lRun1 = lRun1 * sc1 + lt1;
#pragma unroll
        for (int nt = 0; nt < 8; nt++) {
            oacc[nt][0] *= sc0; oacc[nt][1] *= sc0;
            oacc[nt][2] *= sc1; oacc[nt][3] *= sc1;
        }

#pragma unroll
        for (int kc = 0; kc < 4; kc++) {
            unsigned a0 = packh2(sacc[2 * kc][0],     sacc[2 * kc][1]);
            unsigned a1 = packh2(sacc[2 * kc][2],     sacc[2 * kc][3]);
            unsigned a2 = packh2(sacc[2 * kc + 1][0], sacc[2 * kc + 1][1]);
            unsigned a3 = packh2(sacc[2 * kc + 1][2], sacc[2 * kc + 1][3]);
            unsigned vf[8][2];
#pragma unroll
            for (int ntp = 0; ntp < 4; ntp++) {
                int nrow = ntp * 16 + bRowOff;           // dim rows of V^T tile
                int c2 = kc * 2 + bKhalf;
                unsigned off = (unsigned)(nrow * 32) +
                               (((unsigned)(c2 * 4)) ^ (((unsigned)nrow & 7u) << 2));
                ldsm_x4(vf[2 * ntp][0], vf[2 * ntp][1],
                        vf[2 * ntp + 1][0], vf[2 * ntp + 1][1], stV + off * 4u);
            }
#pragma unroll
            for (int nt = 0; nt < 8; nt++)
                HMMA16816(oacc[nt], a0, a1, a2, a3, vf[nt][0], vf[nt][1]);
        }

        __syncthreads();   // 2-deep buffer: must drain readers before refill
        if (kt + 2 < 8) { issueK(kt + 2); issueV(kt + 2); }
        cpa_commit();
    }

#pragma unroll
    for (int o = 1; o <= 2; o <<= 1) {
        lRun0 += __shfl_xor_sync(0xffffffffu, lRun0, o);
        lRun1 += __shfl_xor_sync(0xffffffffu, lRun1, o);
    }
    const float inv0 = 1.f / lRun0;
    const float inv1 = 1.f / lRun1;

    float* xb = x + ((size_t)b * SEQ + qt * 128) * DMODEL + h * HDIM;
#pragma unroll
    for (int nt = 0; nt < 8; nt++) {
        int col = nt * 8 + lr * 2;
        float2 c0 = *(const float2*)(xb + (size_t)r0 * DMODEL + col);
        float2 c1 = *(const float2*)(xb + (size_t)(r0 + 8) * DMODEL + col);
        c0.x += oacc[nt][0] * inv0; c0.y += oacc[nt][1] * inv0;
        c1.x += oacc[nt][2] * inv1; c1.y += oacc[nt][3] * inv1;
        *(float2*)(xb + (size_t)r0 * DMODEL + col) = c0;
        *(float2*)(xb + (size_t)(r0 + 8) * DMODEL + col) = c1;
    }
}

// ---------------- launch ----------------------------------------------------
extern "C" void kernel_launch(void* const* d_in, const int* in_sizes, int n_in,
                              void* d_out, int out_size)
{
    const float* x_in = (const float*)d_in[0];
    const float* Wq = (const float*)d_in[1];
    const float* bq = (const float*)d_in[2];
    const float* Wk = (const float*)d_in[3];
    const float* bk = (const float*)d_in[4];
    const float* Wv = (const float*)d_in[5];
    const float* bv = (const float*)d_in[6];
    const float* g1 = (const float*)d_in[7];
    const float* be1 = (const float*)d_in[8];
    const float* g2 = (const float*)d_in[9];
    const float* be2 = (const float*)d_in[10];
    const float* W0 = (const float*)d_in[11];
    const float* b0 = (const float*)d_in[12];
    const float* W1 = (const float*)d_in[13];
    const float* b1 = (const float*)d_in[14];

    float* x = (float*)d_out;

    void *p_xln, *p_q, *p_k, *p_vt, *p_h1;
    void *p_wq, *p_wk, *p_wv, *p_w0, *p_w1;
    cudaGetSymbolAddress(&p_xln, g_xln);
    cudaGetSymbolAddress(&p_q, g_q);
    cudaGetSymbolAddress(&p_k, g_k);
    cudaGetSymbolAddress(&p_vt, g_vt);
    cudaGetSymbolAddress(&p_h1, g_h1);
    cudaGetSymbolAddress(&p_wq, g_wqT);
    cudaGetSymbolAddress(&p_wk, g_wkT);
    cudaGetSymbolAddress(&p_wv, g_wvT);
    cudaGetSymbolAddress(&p_w0, g_w0T);
    cudaGetSymbolAddress(&p_w1, g_w1T);
    __half* xln = (__half*)p_xln;
    __half* q = (__half*)p_q;
    __half* k = (__half*)p_k;
    __half* vt = (__half*)p_vt;
    __half* h1 = (__half*)p_h1;
    __half* wqT = (__half*)p_wq;
    __half* wkT = (__half*)p_wk;
    __half* wvT = (__half*)p_wv;
    __half* w0T = (__half*)p_w0;
    __half* w1T = (__half*)p_w1;

    cudaFuncSetAttribute(fattn_kernel, cudaFuncAttributeMaxDynamicSharedMemorySize,
                         FA_SMEM_BYTES);
    cudaFuncSetAttribute(h_gemm_qkv_kernel, cudaFuncAttributeMaxDynamicSharedMemorySize,
                         HGEMM_SMEM_128);
    cudaFuncSetAttribute(h_gemm_kernel<4,1>, cudaFuncAttributeMaxDynamicSharedMemorySize,
                         HGEMM_SMEM_128);
    cudaFuncSetAttribute(h_gemm_kernel<2,2>, cudaFuncAttributeMaxDynamicSharedMemorySize,
                         HGEMM_SMEM_64);

    cudaMemcpyAsync(x, x_in, (size_t)NTOK * DMODEL * sizeof(float),
                    cudaMemcpyDeviceToDevice, 0);

    dim3 tb(32, 8);
    transpose_h_kernel<<<dim3(DMODEL/32, DMODEL/32), tb>>>(Wq, wqT, DMODEL, DMODEL);
    transpose_h_kernel<<<dim3(DMODEL/32, DMODEL/32), tb>>>(Wk, wkT, DMODEL, DMODEL);
    transpose_h_kernel<<<dim3(DMODEL/32, DMODEL/32), tb>>>(Wv, wvT, DMODEL, DMODEL);
    transpose_h_kernel<<<dim3(FFDIM/32, DMODEL/32), tb>>>(W0, w0T, DMODEL, FFDIM);
    transpose_h_kernel<<<dim3(DMODEL/32, FFDIM/32), tb>>>(W1, w1T, FFDIM, DMODEL);

    const dim3 gemmQKV(DMODEL / 128, NTOK / 128, 3);  // (6,16,3)
    const dim3 gemmFF1(FFDIM / 128, NTOK / 128);      // (24,16)
    const dim3 gemmFF2(DMODEL / 128, NTOK / 64);      // (6,32)
    const dim3 attnGrid(SEQ / 128, BATCH * NHEAD);    // (4,48)

    for (int blk = 0; blk < NBLOCKS; blk++) {
        ln_kernel<<<NTOK / 8, 256>>>(x, g1, be1, xln);
        h_gemm_qkv_kernel<<<gemmQKV, 256, HGEMM_SMEM_128>>>(
            xln, wqT, wkT, wvT, bq, bk, bv, q, k, vt);
        fattn_kernel<<<attnGrid, 256, FA_SMEM_BYTES>>>(q, k, vt, x);
        ln_kernel<<<NTOK / 8, 256>>>(x, g2, be2, xln);
        h_gemm_kernel<4,1><<<gemmFF1, 256, HGEMM_SMEM_128>>>(
            xln, w0T, b0, (void*)h1, FFDIM, DMODEL);
        h_gemm_kernel<2,2><<<gemmFF2, 256, HGEMM_SMEM_64>>>(
            h1, w1T, b1, (void*)x, DMODEL, FFDIM);
    }
}

// round 13
// speedup vs baseline: 1.0042x; 1.0042x over previous
#include <cuda_runtime.h>
#include <cuda_fp16.h>
#include <math.h>
#include <stdint.h>

// Problem constants
#define BATCH 4
#define SEQ   512
#define DMODEL 768
#define FFDIM 3072
#define NHEAD 12
#define HDIM  64
#define NTOK  (BATCH*SEQ)          // 2048
#define NBLOCKS 12

// ---------------- scratch (device globals; no allocation allowed) -----------
__device__ __half g_xln[NTOK * DMODEL];
__device__ __half g_q  [NTOK * DMODEL];
__device__ __half g_k  [NTOK * DMODEL];
__device__ __half g_vt [NTOK * DMODEL];   // per (b,h): [64 dims][512 tokens]
__device__ __half g_h1 [NTOK * FFDIM];
// fp16, TRANSPOSED weights: wt[n][k] = half(W[k][n])
__device__ __half g_wqT[DMODEL * DMODEL];
__device__ __half g_wkT[DMODEL * DMODEL];
__device__ __half g_wvT[DMODEL * DMODEL];
__device__ __half g_w0T[FFDIM * DMODEL];
__device__ __half g_w1T[DMODEL * FFDIM];

__device__ __forceinline__ void cpa16(unsigned dst, const void* src) {
    asm volatile("cp.async.cg.shared.global [%0], [%1], 16;\n" :: "r"(dst), "l"(src));
}
__device__ __forceinline__ void cpa_commit() {
    asm volatile("cp.async.commit_group;\n" ::: "memory");
}
template <int N>
__device__ __forceinline__ void cpa_wait() {
    asm volatile("cp.async.wait_group %0;\n" :: "n"(N) : "memory");
}
__device__ __forceinline__ unsigned smem_u32(const void* p) {
    unsigned r;
    asm("{ .reg .u64 t; cvta.to.shared.u64 t, %1; cvt.u32.u64 %0, t; }"
        : "=r"(r) : "l"(p));
    return r;
}
__device__ __forceinline__ unsigned packh2(float a, float b) {
    __half2 h = __floats2half2_rn(a, b);
    return *(unsigned*)&h;
}
__device__ __forceinline__ void ldsm_x4(unsigned& r0, unsigned& r1,
                                        unsigned& r2, unsigned& r3, unsigned addr) {
    asm volatile("ldmatrix.sync.aligned.m8n8.x4.shared.b16 {%0,%1,%2,%3}, [%4];"
        : "=r"(r0), "=r"(r1), "=r"(r2), "=r"(r3) : "r"(addr));
}

#define HMMA16816(acc, a0, a1, a2, a3, b0, b1) \
    asm volatile( \
        "mma.sync.aligned.m16n8k16.row.col.f32.f16.f16.f32 " \
        "{%0,%1,%2,%3}, {%4,%5,%6,%7}, {%8,%9}, {%0,%1,%2,%3};" \
        : "+f"((acc)[0]), "+f"((acc)[1]), "+f"((acc)[2]), "+f"((acc)[3]) \
        : "r"(a0), "r"(a1), "r"(a2), "r"(a3), "r"(b0), "r"(b1))

// ---------------- batched prep: 5 weight transposes + x copy, ONE launch ----
// Segments (32x32 tiles, block (32,8)):
//   [0,576)      Wq -> wqT      (24x24 tiles)
//   [576,1152)   Wk -> wkT
//   [1152,1728)  Wv -> wvT
//   [1728,4032)  W0 -> w0T      (96x24 tiles: C=FFDIM)
//   [4032,6336)  W1 -> w1T      (24x96 tiles: C=DMODEL, R=FFDIM)
//   [6336,7872)  x_in -> x copy (1536 blocks x 1024 floats)
__device__ __forceinline__ void transpose_tile(
    const float* __restrict__ src, __half* __restrict__ dst,
    int R, int C, int tileId)
{
    __shared__ float t[32][33];
    const int ctiles = C / 32;
    const int c0 = (tileId % ctiles) * 32;
    const int r0 = (tileId / ctiles) * 32;
    const int tx = threadIdx.x, ty = threadIdx.y;
#pragma unroll
    for (int i = 0; i < 4; i++)
        t[ty + 8 * i][tx] = src[(size_t)(r0 + ty + 8 * i) * C + c0 + tx];
    __syncthreads();
#pragma unroll
    for (int i = 0; i < 4; i++)
        dst[(size_t)(c0 + ty + 8 * i) * R + r0 + tx] = __float2half_rn(t[tx][ty + 8 * i]);
}

__global__ __launch_bounds__(256) void prep_kernel(
    const float* __restrict__ x_in, float* __restrict__ x,
    const float* __restrict__ Wq, const float* __restrict__ Wk,
    const float* __restrict__ Wv, const float* __restrict__ W0,
    const float* __restrict__ W1,
    __half* __restrict__ wqT, __half* __restrict__ wkT, __half* __restrict__ wvT,
    __half* __restrict__ w0T, __half* __restrict__ w1T)
{
    const int bid = blockIdx.x;
    if (bid < 576) {
        transpose_tile(Wq, wqT, DMODEL, DMODEL, bid);
    } else if (bid < 1152) {
        transpose_tile(Wk, wkT, DMODEL, DMODEL, bid - 576);
    } else if (bid < 1728) {
        transpose_tile(Wv, wvT, DMODEL, DMODEL, bid - 1152);
    } else if (bid < 4032) {
        transpose_tile(W0, w0T, DMODEL, FFDIM, bid - 1728);
    } else if (bid < 6336) {
        transpose_tile(W1, w1T, FFDIM, DMODEL, bid - 4032);
    } else {
        const int tid = threadIdx.y * 32 + threadIdx.x;
        const size_t off = (size_t)(bid - 6336) * 1024 + (size_t)tid * 4;
        *(float4*)(x + off) = *(const float4*)(x_in + off);
    }
}
#define PREP_GRID 7872

// ---------------- LayerNorm: warp per row; outputs fp16 ---------------------
__global__ __launch_bounds__(256) void ln_kernel(
    const float* __restrict__ x, const float* __restrict__ g,
    const float* __restrict__ be, __half* __restrict__ y)
{
    const int wid = threadIdx.x >> 5, lane = threadIdx.x & 31;
    const int r = blockIdx.x * 8 + wid;
    const float* xr = x + (size_t)r * DMODEL;

    float4 v[6];
    float s = 0.f, s2 = 0.f;
#pragma unroll
    for (int i = 0; i < 6; i++) {
        v[i] = *(const float4*)(xr + (i * 32 + lane) * 4);
        s  += v[i].x + v[i].y + v[i].z + v[i].w;
        s2 += v[i].x * v[i].x + v[i].y * v[i].y + v[i].z * v[i].z + v[i].w * v[i].w;
    }
#pragma unroll
    for (int o = 16; o > 0; o >>= 1) {
        s  += __shfl_xor_sync(0xffffffffu, s,  o);
        s2 += __shfl_xor_sync(0xffffffffu, s2, o);
    }
    const float mu  = s  * (1.f / DMODEL);
    const float var = s2 * (1.f / DMODEL) - mu * mu;
    const float inv = rsqrtf(var + 1e-5f);
    __half* yr = y + (size_t)r * DMODEL;
#pragma unroll
    for (int i = 0; i < 6; i++) {
        const int col = (i * 32 + lane) * 4;
        float4 gg = *(const float4*)(g + col);
        float4 bb = *(const float4*)(be + col);
        unsigned p0 = packh2((v[i].x - mu) * inv * gg.x + bb.x,
                             (v[i].y - mu) * inv * gg.y + bb.y);
        unsigned p1 = packh2((v[i].z - mu) * inv * gg.z + bb.z,
                             (v[i].w - mu) * inv * gg.w + bb.w);
        uint2 o; o.x = p0; o.y = p1;
        *(uint2*)(yr + col) = o;
    }
}

// ===================== FP16 tensor-core GEMM ================================
#define BKH 64
#define NSTAGE 3

template <int MT, int MODE>
__device__ __forceinline__ void h_gemm_core(
    const __half* __restrict__ A, const __half* __restrict__ BT,
    const float* __restrict__ bias, void* __restrict__ Cv,
    int N, int K)
{
    constexpr int BMv  = MT * 32;
    constexpr int ASTG = BMv * 32;
    constexpr int BSTG = 128 * 32;

    extern __shared__ unsigned smemU[];
    unsigned* As = smemU;
    unsigned* Bs = smemU + NSTAGE * ASTG;
    const unsigned asBase = smem_u32(As);
    const unsigned bsBase = smem_u32(Bs);

    const int tid  = threadIdx.x;
    const int lane = tid & 31;
    const int wid  = tid >> 5;
    const int wm   = wid >> 2;
    const int wn   = wid & 3;
    const int rowBase = blockIdx.y * BMv;
    const int colBase = blockIdx.x * 128;
    const int lq = lane >> 2;
    const int lr = lane & 3;

    const int aRowOff = ((lane >> 3) & 1) * 8 + (lane & 7);
    const int aKhalf  = lane >> 4;
    const int bRowOff = ((lane >> 4) & 1) * 8 + (lane & 7);
    const int bKhalf  = (lane >> 3) & 1;

    auto issue = [&](int c) {
        const int st = c % NSTAGE;
        const int k0 = c * BKH;
#pragma unroll
        for (int i = 0; i < MT; i++) {
            int fi = tid + i * 256;
            int r = fi >> 3, c8 = fi & 7;
            unsigned u = (unsigned)(c8 * 4) ^ (((unsigned)r & 7u) << 2);
            cpa16(asBase + (st * ASTG + r * 32 + u) * 4u,
                  A + (size_t)(rowBase + r) * K + k0 + c8 * 8);
        }
#pragma unroll
        for (int i = 0; i < 4; i++) {
            int fi = tid + i * 256;
            int r = fi >> 3, c8 = fi & 7;
            unsigned u = (unsigned)(c8 * 4) ^ (((unsigned)r & 7u) << 2);
            cpa16(bsBase + (st * BSTG + r * 32 + u) * 4u,
                  BT + (size_t)(colBase + r) * K + k0 + c8 * 8);
        }
    };

    float acc[MT][4][4];
#pragma unroll
    for (int i = 0; i < MT; i++)
#pragma unroll
        for (int j = 0; j < 4; j++)
#pragma unroll
            for (int t = 0; t < 4; t++) acc[i][j][t] = 0.f;

    const int nch = K / BKH;
    issue(0); cpa_commit();
    issue(1); cpa_commit();

    for (int c = 0; c < nch; c++) {
        cpa_wait<1>();
        __syncthreads();
        if (c + 2 < nch) issue(c + 2);
        cpa_commit();

        const unsigned stA = asBase + (unsigned)((c % NSTAGE) * ASTG) * 4u;
        const unsigned stB = bsBase + (unsigned)((c % NSTAGE) * BSTG) * 4u;
#pragma unroll
        for (int ks = 0; ks < 4; ks++) {
            unsigned af[MT][4];
#pragma unroll
            for (int mt = 0; mt < MT; mt++) {
                int r = wm * (MT * 16) + mt * 16 + aRowOff;
                int c2 = ks * 2 + aKhalf;
                unsigned off = (unsigned)(r * 32) + (((unsigned)(c2 * 4)) ^ (((unsigned)r & 7u) << 2));
                ldsm_x4(af[mt][0], af[mt][1], af[mt][2], af[mt][3], stA + off * 4u);
            }
            unsigned bf[4][2];
#pragma unroll
            for (int ntp = 0; ntp < 2; ntp++) {
                int nrow = wn * 32 + ntp * 16 + bRowOff;
                int c2 = ks * 2 + bKhalf;
                unsigned off = (unsigned)(nrow * 32) + (((unsigned)(c2 * 4)) ^ (((unsigned)nrow & 7u) << 2));
                ldsm_x4(bf[2 * ntp][0], bf[2 * ntp][1],
                        bf[2 * ntp + 1][0], bf[2 * ntp + 1][1], stB + off * 4u);
            }
#pragma unroll
            for (int nt = 0; nt < 4; nt++)
#pragma unroll
                for (int mt = 0; mt < MT; mt++)
                    HMMA16816(acc[mt][nt], af[mt][0], af[mt][1], af[mt][2], af[mt][3],
                              bf[nt][0], bf[nt][1]);
        }
        // (no trailing __syncthreads: 3-stage pipeline guarantees safety)
    }

#pragma unroll
    for (int mt = 0; mt < MT; mt++) {
        int row = rowBase + wm * (MT * 16) + mt * 16 + lq;
#pragma unroll
        for (int nt = 0; nt < 4; nt++) {
            int col = colBase + wn * 32 + nt * 8 + lr * 2;
            float b0 = bias[col], b1 = bias[col + 1];
            float v00 = acc[mt][nt][0] + b0;
            float v01 = acc[mt][nt][1] + b1;
            float v10 = acc[mt][nt][2] + b0;
            float v11 = acc[mt][nt][3] + b1;
            if (MODE == 1) {
                v00 = 0.5f * v00 * (1.0f + erff(v00 * 0.70710678118654752f));
                v01 = 0.5f * v01 * (1.0f + erff(v01 * 0.70710678118654752f));
                v10 = 0.5f * v10 * (1.0f + erff(v10 * 0.70710678118654752f));
                v11 = 0.5f * v11 * (1.0f + erff(v11 * 0.70710678118654752f));
            }
            if (MODE == 0 || MODE == 1) {
                __half* C = (__half*)Cv;
                *(unsigned*)(C + (size_t)row * N + col)       = packh2(v00, v01);
                *(unsigned*)(C + (size_t)(row + 8) * N + col) = packh2(v10, v11);
            } else if (MODE == 2) {
                float* C = (float*)Cv;
                float2 c0 = *(const float2*)(C + (size_t)row * N + col);
                float2 c1 = *(const float2*)(C + (size_t)(row + 8) * N + col);
                c0.x += v00; c0.y += v01;
                c1.x += v10; c1.y += v11;
                *(float2*)(C + (size_t)row * N + col) = c0;
                *(float2*)(C + (size_t)(row + 8) * N + col) = c1;
            } else {  // MODE 4: V transposed store -> vt[(b*DMODEL+col)*SEQ + tok]
                __half* C = (__half*)Cv;
                int bb = row >> 9;
                int tok = row & 511;
                size_t base = ((size_t)(bb * DMODEL + col)) * SEQ;
                C[base + tok]           = __float2half_rn(v00);
                C[base + SEQ + tok]     = __float2half_rn(v01);
                C[base + tok + 8]       = __float2half_rn(v10);
                C[base + SEQ + tok + 8] = __float2half_rn(v11);
            }
        }
    }
}

template <int MT, int MODE>
__global__ __launch_bounds__(256) void h_gemm_kernel(
    const __half* __restrict__ A, const __half* __restrict__ BT,
    const float* __restrict__ bias, void* __restrict__ C, int N, int K)
{
    h_gemm_core<MT, MODE>(A, BT, bias, C, N, K);
}

__global__ __launch_bounds__(256) void h_gemm_qkv_kernel(
    const __half* __restrict__ A,
    const __half* __restrict__ WqT, const __half* __restrict__ WkT,
    const __half* __restrict__ WvT,
    const float* __restrict__ bq, const float* __restrict__ bk,
    const float* __restrict__ bv,
    __half* __restrict__ q, __half* __restrict__ k, __half* __restrict__ vt)
{
    if (blockIdx.z == 0)      h_gemm_core<4, 0>(A, WqT, bq, (void*)q,  DMODEL, DMODEL);
    else if (blockIdx.z == 1) h_gemm_core<4, 0>(A, WkT, bk, (void*)k,  DMODEL, DMODEL);
    else                      h_gemm_core<4, 4>(A, WvT, bv, (void*)vt, DMODEL, DMODEL);
}

#define HGEMM_SMEM_128 (NSTAGE * (128*32 + 128*32) * 4)   // 98304
#define HGEMM_SMEM_64  (NSTAGE * (64*32  + 128*32) * 4)   // 73728

// ===================== Flash attention (fp16 mma, online softmax) ===========
#define FA_SMEM_BYTES ((4096 + 2*2048 + 2*2048) * 4)   // 49152

__global__ __launch_bounds__(256) void fattn_kernel(
    const __half* __restrict__ q, const __half* __restrict__ k,
    const __half* __restrict__ vt, float* __restrict__ x)
{
    extern __shared__ unsigned sm[];
    unsigned* Qs = sm;                 // [128][32]
    const unsigned qsB = smem_u32(Qs);
    const unsigned ksB = qsB + 4096 * 4u;   // [2][64][32]
    const unsigned vsB = qsB + 8192 * 4u;   // [2][64][32]

    const int tid = threadIdx.x;
    const int lane = tid & 31;
    const int wid = tid >> 5;
    const int lq = lane >> 2;
    const int lr = lane & 3;

    const int aRowOff = ((lane >> 3) & 1) * 8 + (lane & 7);
    const int aKhalf  = lane >> 4;
    const int bRowOff = ((lane >> 4) & 1) * 8 + (lane & 7);
    const int bKhalf  = (lane >> 3) & 1;

    const int qt = blockIdx.x;
    const int bh = blockIdx.y;
    const int b = bh / NHEAD, h = bh % NHEAD;

    const __half* qb  = q  + ((size_t)b * SEQ + qt * 128) * DMODEL + h * HDIM;
    const __half* kb  = k  + (size_t)b * SEQ * DMODEL + h * HDIM;
    const __half* vtb = vt + (size_t)bh * HDIM * SEQ;

    auto issueQ = [&]() {
#pragma unroll
        for (int i = 0; i < 4; i++) {
            int fi = tid + i * 256;
            int r = fi >> 3, c8 = fi & 7;
            unsigned u = (unsigned)(c8 * 4) ^ (((unsigned)r & 7u) << 2);
            cpa16(qsB + (r * 32 + u) * 4u, qb + (size_t)r * DMODEL + c8 * 8);
        }
    };
    auto issueK = [&](int kt) {
#pragma unroll
        for (int i = 0; i < 2; i++) {
            int fi = tid + i * 256;
            int r = fi >> 3, c8 = fi & 7;
            unsigned u = (unsigned)(c8 * 4) ^ (((unsigned)r & 7u) << 2);
            cpa16(ksB + ((kt & 1) * 2048 + r * 32 + u) * 4u,
                  kb + (size_t)(kt * 64 + r) * DMODEL + c8 * 8);
        }
    };
    auto issueV = [&](int kt) {
#pragma unroll
        for (int i = 0; i < 2; i++) {
            int fi = tid + i * 256;
            int r = fi >> 3, c8 = fi & 7;
            unsigned u = (unsigned)(c8 * 4) ^ (((unsigned)r & 7u) << 2);
            cpa16(vsB + ((kt & 1) * 2048 + r * 32 + u) * 4u,
                  vtb + (size_t)r * SEQ + kt * 64 + c8 * 8);
        }
    };

    issueQ(); issueK(0); issueV(0); cpa_commit();
    issueK(1); issueV(1); cpa_commit();

    float oacc[8][4];
#pragma unroll
    for (int nt = 0; nt < 8; nt++)
#pragma unroll
        for (int t = 0; t < 4; t++) oacc[nt][t] = 0.f;
    float mRun0 = -1e30f, mRun1 = -1e30f;
    float lRun0 = 0.f, lRun1 = 0.f;

    const int r0 = wid * 16 + lq;
    unsigned qf[4][4];   // Q fragments, loaded once at kt==0

    for (int kt = 0; kt < 8; kt++) {
        cpa_wait<1>();
        __syncthreads();

        if (kt == 0) {
#pragma unroll
            for (int ks = 0; ks < 4; ks++) {
                int r = wid * 16 + aRowOff;
                int c2 = ks * 2 + aKhalf;
                unsigned off = (unsigned)(r * 32) +
                               (((unsigned)(c2 * 4)) ^ (((unsigned)r & 7u) << 2));
                ldsm_x4(qf[ks][0], qf[ks][1], qf[ks][2], qf[ks][3], qsB + off * 4u);
            }
        }

        float sacc[8][4];
#pragma unroll
        for (int nt = 0; nt < 8; nt++)
#pragma unroll
            for (int t = 0; t < 4; t++) sacc[nt][t] = 0.f;

        const unsigned stK = ksB + (unsigned)((kt & 1) * 2048) * 4u;
        const unsigned stV = vsB + (unsigned)((kt & 1) * 2048) * 4u;
#pragma unroll
        for (int ks = 0; ks < 4; ks++) {
            unsigned kf[8][2];
#pragma unroll
            for (int ntp = 0; ntp < 4; ntp++) {
                int nrow = ntp * 16 + bRowOff;
                int c2 = ks * 2 + bKhalf;
                unsigned off = (unsigned)(nrow * 32) +
                               (((unsigned)(c2 * 4)) ^ (((unsigned)nrow & 7u) << 2));
                ldsm_x4(kf[2 * ntp][0], kf[2 * ntp][1],
                        kf[2 * ntp + 1][0], kf[2 * ntp + 1][1], stK + off * 4u);
            }
#pragma unroll
            for (int nt = 0; nt < 8; nt++)
                HMMA16816(sacc[nt], qf[ks][0], qf[ks][1], qf[ks][2], qf[ks][3],
                          kf[nt][0], kf[nt][1]);
        }

        float m0 = -1e30f, m1 = -1e30f;
#pragma unroll
        for (int nt = 0; nt < 8; nt++) {
            sacc[nt][0] *= 0.125f; sacc[nt][1] *= 0.125f;
            sacc[nt][2] *= 0.125f; sacc[nt][3] *= 0.125f;
            m0 = fmaxf(m0, fmaxf(sacc[nt][0], sacc[nt][1]));
            m1 = fmaxf(m1, fmaxf(sacc[nt][2], sacc[nt][3]));
        }
#pragma unroll
        for (int o = 1; o <= 2; o <<= 1) {
            m0 = fmaxf(m0, __shfl_xor_sync(0xffffffffu, m0, o));
            m1 = fmaxf(m1, __shfl_xor_sync(0xffffffffu, m1, o));
        }
        const float nm0 = fmaxf(mRun0, m0);
        const float nm1 = fmaxf(mRun1, m1);
        const float sc0 = __expf(mRun0 - nm0);
        const float sc1 = __expf(mRun1 - nm1);
        mRun0 = nm0; mRun1 = nm1;

        float lt0 = 0.f, lt1 = 0.f;
#pragma unroll
        for (int nt = 0; nt < 8; nt++) {
            sacc[nt][0] = __expf(sacc[nt][0] - nm0);
            sacc[nt][1] = __expf(sacc[nt][1] - nm0);
            sacc[nt][2] = __expf(sacc[nt][2] - nm1);
            sacc[nt][3] = __expf(sacc[nt][3] - nm1);
            lt0 += sacc[nt][0] + sacc[nt][1];
            lt1 += sacc[nt][2] + sacc[nt][3];
        }
        lRun0 = lRun0 * sc0 + lt0;
        lRun1 = lRun1 * sc1 + lt1;
#pragma unroll
        for (int nt = 0; nt < 8; nt++) {
            oacc[nt][0] *= sc0; oacc[nt][1] *= sc0;
            oacc[nt][2] *= sc1; oacc[nt][3] *= sc1;
        }

#pragma unroll
        for (int kc = 0; kc < 4; kc++) {
            unsigned a0 = packh2(sacc[2 * kc][0],     sacc[2 * kc][1]);
            unsigned a1 = packh2(sacc[2 * kc][2],     sacc[2 * kc][3]);
            unsigned a2 = packh2(sacc[2 * kc + 1][0], sacc[2 * kc + 1][1]);
            unsigned a3 = packh2(sacc[2 * kc + 1][2], sacc[2 * kc + 1][3]);
            unsigned vf[8][2];
#pragma unroll
            for (int ntp = 0; ntp < 4; ntp++) {
                int nrow = ntp * 16 + bRowOff;           // dim rows of V^T tile
                int c2 = kc * 2 + bKhalf;
                unsigned off = (unsigned)(nrow * 32) +
                               (((unsigned)(c2 * 4)) ^ (((unsigned)nrow & 7u) << 2));
                ldsm_x4(vf[2 * ntp][0], vf[2 * ntp][1],
                        vf[2 * ntp + 1][0], vf[2 * ntp + 1][1], stV + off * 4u);
            }
#pragma unroll
            for (int nt = 0; nt < 8; nt++)
                HMMA16816(oacc[nt], a0, a1, a2, a3, vf[nt][0], vf[nt][1]);
        }

        __syncthreads();   // 2-deep buffer: must drain readers before refill
        if (kt + 2 < 8) { issueK(kt + 2); issueV(kt + 2); }
        cpa_commit();
    }

#pragma unroll
    for (int o = 1; o <= 2; o <<= 1) {
        lRun0 += __shfl_xor_sync(0xffffffffu, lRun0, o);
        lRun1 += __shfl_xor_sync(0xffffffffu, lRun1, o);
    }
    const float inv0 = 1.f / lRun0;
    const float inv1 = 1.f / lRun1;

    float* xb = x + ((size_t)b * SEQ + qt * 128) * DMODEL + h * HDIM;
#pragma unroll
    for (int nt = 0; nt < 8; nt++) {
        int col = nt * 8 + lr * 2;
        float2 c0 = *(const float2*)(xb + (size_t)r0 * DMODEL + col);
        float2 c1 = *(const float2*)(xb + (size_t)(r0 + 8) * DMODEL + col);
        c0.x += oacc[nt][0] * inv0; c0.y += oacc[nt][1] * inv0;
        c1.x += oacc[nt][2] * inv1; c1.y += oacc[nt][3] * inv1;
        *(float2*)(xb + (size_t)r0 * DMODEL + col) = c0;
        *(float2*)(xb + (size_t)(r0 + 8) * DMODEL + col) = c1;
    }
}

// ---------------- launch ----------------------------------------------------
extern "C" void kernel_launch(void* const* d_in, const int* in_sizes, int n_in,
                              void* d_out, int out_size)
{
    const float* x_in = (const float*)d_in[0];
    const float* Wq = (const float*)d_in[1];
    const float* bq = (const float*)d_in[2];
    const float* Wk = (const float*)d_in[3];
    const float* bk = (const float*)d_in[4];
    const float* Wv = (const float*)d_in[5];
    const float* bv = (const float*)d_in[6];
    const float* g1 = (const float*)d_in[7];
    const float* be1 = (const float*)d_in[8];
    const float* g2 = (const float*)d_in[9];
    const float* be2 = (const float*)d_in[10];
    const float* W0 = (const float*)d_in[11];
    const float* b0 = (const float*)d_in[12];
    const float* W1 = (const float*)d_in[13];
    const float* b1 = (const float*)d_in[14];

    float* x = (float*)d_out;

    void *p_xln, *p_q, *p_k, *p_vt, *p_h1;
    void *p_wq, *p_wk, *p_wv, *p_w0, *p_w1;
    cudaGetSymbolAddress(&p_xln, g_xln);
    cudaGetSymbolAddress(&p_q, g_q);
    cudaGetSymbolAddress(&p_k, g_k);
    cudaGetSymbolAddress(&p_vt, g_vt);
    cudaGetSymbolAddress(&p_h1, g_h1);
    cudaGetSymbolAddress(&p_wq, g_wqT);
    cudaGetSymbolAddress(&p_wk, g_wkT);
    cudaGetSymbolAddress(&p_wv, g_wvT);
    cudaGetSymbolAddress(&p_w0, g_w0T);
    cudaGetSymbolAddress(&p_w1, g_w1T);
    __half* xln = (__half*)p_xln;
    __half* q = (__half*)p_q;
    __half* k = (__half*)p_k;
    __half* vt = (__half*)p_vt;
    __half* h1 = (__half*)p_h1;
    __half* wqT = (__half*)p_wq;
    __half* wkT = (__half*)p_wk;
    __half* wvT = (__half*)p_wv;
    __half* w0T = (__half*)p_w0;
    __half* w1T = (__half*)p_w1;

    cudaFuncSetAttribute(fattn_kernel, cudaFuncAttributeMaxDynamicSharedMemorySize,
                         FA_SMEM_BYTES);
    cudaFuncSetAttribute(h_gemm_qkv_kernel, cudaFuncAttributeMaxDynamicSharedMemorySize,
                         HGEMM_SMEM_128);
    cudaFuncSetAttribute(h_gemm_kernel<4,1>, cudaFuncAttributeMaxDynamicSharedMemorySize,
                         HGEMM_SMEM_128);
    cudaFuncSetAttribute(h_gemm_kernel<2,2>, cudaFuncAttributeMaxDynamicSharedMemorySize,
                         HGEMM_SMEM_64);

    // one launch: all weight transposes + x copy
    prep_kernel<<<PREP_GRID, dim3(32, 8)>>>(
        x_in, x, Wq, Wk, Wv, W0, W1, wqT, wkT, wvT, w0T, w1T);

    const dim3 gemmQKV(DMODEL / 128, NTOK / 128, 3);  // (6,16,3)
    const dim3 gemmFF1(FFDIM / 128, NTOK / 128);      // (24,16)
    const dim3 gemmFF2(DMODEL / 128, NTOK / 64);      // (6,32)
    const dim3 attnGrid(SEQ / 128, BATCH * NHEAD);    // (4,48)

    for (int blk = 0; blk < NBLOCKS; blk++) {
        ln_kernel<<<NTOK / 8, 256>>>(x, g1, be1, xln);
        h_gemm_qkv_kernel<<<gemmQKV, 256, HGEMM_SMEM_128>>>(
            xln, wqT, wkT, wvT, bq, bk, bv, q, k, vt);
        fattn_kernel<<<attnGrid, 256, FA_SMEM_BYTES>>>(q, k, vt, x);
        ln_kernel<<<NTOK / 8, 256>>>(x, g2, be2, xln);
        h_gemm_kernel<4,1><<<gemmFF1, 256, HGEMM_SMEM_128>>>(
            xln, w0T, b0, (void*)h1, FFDIM, DMODEL);
        h_gemm_kernel<2,2><<<gemmFF2, 256, HGEMM_SMEM_64>>>(
            h1, w1T, b1, (void*)x, DMODEL, FFDIM);
    }
}

// round 14
// speedup vs baseline: 1.0365x; 1.0322x over previous
#include <cuda_runtime.h>
#include <cuda_fp16.h>
#include <math.h>
#include <stdint.h>

// Problem constants
#define BATCH 4
#define SEQ   512
#define DMODEL 768
#define FFDIM 3072
#define NHEAD 12
#define HDIM  64
#define NTOK  (BATCH*SEQ)          // 2048
#define NBLOCKS 12

// ---------------- scratch (device globals; no allocation allowed) -----------
__device__ __half g_xln[NTOK * DMODEL];
__device__ __half g_q  [NTOK * DMODEL];
__device__ __half g_k  [NTOK * DMODEL];
__device__ __half g_vt [NTOK * DMODEL];   // per (b,h): [64 dims][512 tokens]
__device__ __half g_h1 [NTOK * FFDIM];
// fp16, TRANSPOSED weights: wt[n][k] = half(W[k][n])
__device__ __half g_wqT[DMODEL * DMODEL];
__device__ __half g_wkT[DMODEL * DMODEL];
__device__ __half g_wvT[DMODEL * DMODEL];
__device__ __half g_w0T[FFDIM * DMODEL];
__device__ __half g_w1T[DMODEL * FFDIM];

__device__ __forceinline__ void cpa16(unsigned dst, const void* src) {
    asm volatile("cp.async.cg.shared.global [%0], [%1], 16;\n" :: "r"(dst), "l"(src));
}
__device__ __forceinline__ void cpa_commit() {
    asm volatile("cp.async.commit_group;\n" ::: "memory");
}
template <int N>
__device__ __forceinline__ void cpa_wait() {
    asm volatile("cp.async.wait_group %0;\n" :: "n"(N) : "memory");
}
__device__ __forceinline__ unsigned smem_u32(const void* p) {
    unsigned r;
    asm("{ .reg .u64 t; cvta.to.shared.u64 t, %1; cvt.u32.u64 %0, t; }"
        : "=r"(r) : "l"(p));
    return r;
}
__device__ __forceinline__ unsigned packh2(float a, float b) {
    __half2 h = __floats2half2_rn(a, b);
    return *(unsigned*)&h;
}
__device__ __forceinline__ void ldsm_x4(unsigned& r0, unsigned& r1,
                                        unsigned& r2, unsigned& r3, unsigned addr) {
    asm volatile("ldmatrix.sync.aligned.m8n8.x4.shared.b16 {%0,%1,%2,%3}, [%4];"
        : "=r"(r0), "=r"(r1), "=r"(r2), "=r"(r3) : "r"(addr));
}

#define HMMA16816(acc, a0, a1, a2, a3, b0, b1) \
    asm volatile( \
        "mma.sync.aligned.m16n8k16.row.col.f32.f16.f16.f32 " \
        "{%0,%1,%2,%3}, {%4,%5,%6,%7}, {%8,%9}, {%0,%1,%2,%3};" \
        : "+f"((acc)[0]), "+f"((acc)[1]), "+f"((acc)[2]), "+f"((acc)[3]) \
        : "r"(a0), "r"(a1), "r"(a2), "r"(a3), "r"(b0), "r"(b1))

// ---------------- batched prep: 5 weight transposes + x copy, ONE launch ----
__device__ __forceinline__ void transpose_tile(
    const float* __restrict__ src, __half* __restrict__ dst,
    int R, int C, int tileId)
{
    __shared__ float t[32][33];
    const int ctiles = C / 32;
    const int c0 = (tileId % ctiles) * 32;
    const int r0 = (tileId / ctiles) * 32;
    const int tx = threadIdx.x, ty = threadIdx.y;
#pragma unroll
    for (int i = 0; i < 4; i++)
        t[ty + 8 * i][tx] = src[(size_t)(r0 + ty + 8 * i) * C + c0 + tx];
    __syncthreads();
#pragma unroll
    for (int i = 0; i < 4; i++)
        dst[(size_t)(c0 + ty + 8 * i) * R + r0 + tx] = __float2half_rn(t[tx][ty + 8 * i]);
}

__global__ __launch_bounds__(256) void prep_kernel(
    const float* __restrict__ x_in, float* __restrict__ x,
    const float* __restrict__ Wq, const float* __restrict__ Wk,
    const float* __restrict__ Wv, const float* __restrict__ W0,
    const float* __restrict__ W1,
    __half* __restrict__ wqT, __half* __restrict__ wkT, __half* __restrict__ wvT,
    __half* __restrict__ w0T, __half* __restrict__ w1T)
{
    const int bid = blockIdx.x;
    if (bid < 576) {
        transpose_tile(Wq, wqT, DMODEL, DMODEL, bid);
    } else if (bid < 1152) {
        transpose_tile(Wk, wkT, DMODEL, DMODEL, bid - 576);
    } else if (bid < 1728) {
        transpose_tile(Wv, wvT, DMODEL, DMODEL, bid - 1152);
    } else if (bid < 4032) {
        transpose_tile(W0, w0T, DMODEL, FFDIM, bid - 1728);
    } else if (bid < 6336) {
        transpose_tile(W1, w1T, FFDIM, DMODEL, bid - 4032);
    } else {
        const int tid = threadIdx.y * 32 + threadIdx.x;
        const size_t off = (size_t)(bid - 6336) * 1024 + (size_t)tid * 4;
        *(float4*)(x + off) = *(const float4*)(x_in + off);
    }
}
#define PREP_GRID 7872

// ---------------- LayerNorm: warp per row; outputs fp16 ---------------------
__global__ __launch_bounds__(256) void ln_kernel(
    const float* __restrict__ x, const float* __restrict__ g,
    const float* __restrict__ be, __half* __restrict__ y)
{
    const int wid = threadIdx.x >> 5, lane = threadIdx.x & 31;
    const int r = blockIdx.x * 8 + wid;
    const float* xr = x + (size_t)r * DMODEL;

    float4 v[6];
    float s = 0.f, s2 = 0.f;
#pragma unroll
    for (int i = 0; i < 6; i++) {
        v[i] = *(const float4*)(xr + (i * 32 + lane) * 4);
        s  += v[i].x + v[i].y + v[i].z + v[i].w;
        s2 += v[i].x * v[i].x + v[i].y * v[i].y + v[i].z * v[i].z + v[i].w * v[i].w;
    }
#pragma unroll
    for (int o = 16; o > 0; o >>= 1) {
        s  += __shfl_xor_sync(0xffffffffu, s,  o);
        s2 += __shfl_xor_sync(0xffffffffu, s2, o);
    }
    const float mu  = s  * (1.f / DMODEL);
    const float var = s2 * (1.f / DMODEL) - mu * mu;
    const float inv = rsqrtf(var + 1e-5f);
    __half* yr = y + (size_t)r * DMODEL;
#pragma unroll
    for (int i = 0; i < 6; i++) {
        const int col = (i * 32 + lane) * 4;
        float4 gg = *(const float4*)(g + col);
        float4 bb = *(const float4*)(be + col);
        unsigned p0 = packh2((v[i].x - mu) * inv * gg.x + bb.x,
                             (v[i].y - mu) * inv * gg.y + bb.y);
        unsigned p1 = packh2((v[i].z - mu) * inv * gg.z + bb.z,
                             (v[i].w - mu) * inv * gg.w + bb.w);
        uint2 o; o.x = p0; o.y = p1;
        *(uint2*)(yr + col) = o;
    }
}

// ===================== FP16 tensor-core GEMM ================================
#define BKH 64
#define NSTAGE 3

template <int MT, int MODE>
__device__ __forceinline__ void h_gemm_core(
    const __half* __restrict__ A, const __half* __restrict__ BT,
    const float* __restrict__ bias, void* __restrict__ Cv,
    int N, int K)
{
    constexpr int BMv  = MT * 32;
    constexpr int ASTG = BMv * 32;
    constexpr int BSTG = 128 * 32;

    extern __shared__ unsigned smemU[];
    unsigned* As = smemU;
    unsigned* Bs = smemU + NSTAGE * ASTG;
    const unsigned asBase = smem_u32(As);
    const unsigned bsBase = smem_u32(Bs);

    const int tid  = threadIdx.x;
    const int lane = tid & 31;
    const int wid  = tid >> 5;
    const int wm   = wid >> 2;
    const int wn   = wid & 3;
    const int rowBase = blockIdx.y * BMv;
    const int colBase = blockIdx.x * 128;
    const int lq = lane >> 2;
    const int lr = lane & 3;

    const int aRowOff = ((lane >> 3) & 1) * 8 + (lane & 7);
    const int aKhalf  = lane >> 4;
    const int bRowOff = ((lane >> 4) & 1) * 8 + (lane & 7);
    const int bKhalf  = (lane >> 3) & 1;

    auto issue = [&](int c) {
        const int st = c % NSTAGE;
        const int k0 = c * BKH;
#pragma unroll
        for (int i = 0; i < MT; i++) {
            int fi = tid + i * 256;
            int r = fi >> 3, c8 = fi & 7;
            unsigned u = (unsigned)(c8 * 4) ^ (((unsigned)r & 7u) << 2);
            cpa16(asBase + (st * ASTG + r * 32 + u) * 4u,
                  A + (size_t)(rowBase + r) * K + k0 + c8 * 8);
        }
#pragma unroll
        for (int i = 0; i < 4; i++) {
            int fi = tid + i * 256;
            int r = fi >> 3, c8 = fi & 7;
            unsigned u = (unsigned)(c8 * 4) ^ (((unsigned)r & 7u) << 2);
            cpa16(bsBase + (st * BSTG + r * 32 + u) * 4u,
                  BT + (size_t)(colBase + r) * K + k0 + c8 * 8);
        }
    };

    float acc[MT][4][4];
#pragma unroll
    for (int i = 0; i < MT; i++)
#pragma unroll
        for (int j = 0; j < 4; j++)
#pragma unroll
            for (int t = 0; t < 4; t++) acc[i][j][t] = 0.f;

    const int nch = K / BKH;
    issue(0); cpa_commit();
    issue(1); cpa_commit();

    for (int c = 0; c < nch; c++) {
        cpa_wait<1>();
        __syncthreads();
        if (c + 2 < nch) issue(c + 2);
        cpa_commit();

        const unsigned stA = asBase + (unsigned)((c % NSTAGE) * ASTG) * 4u;
        const unsigned stB = bsBase + (unsigned)((c % NSTAGE) * BSTG) * 4u;
#pragma unroll
        for (int ks = 0; ks < 4; ks++) {
            unsigned af[MT][4];
#pragma unroll
            for (int mt = 0; mt < MT; mt++) {
                int r = wm * (MT * 16) + mt * 16 + aRowOff;
                int c2 = ks * 2 + aKhalf;
                unsigned off = (unsigned)(r * 32) + (((unsigned)(c2 * 4)) ^ (((unsigned)r & 7u) << 2));
                ldsm_x4(af[mt][0], af[mt][1], af[mt][2], af[mt][3], stA + off * 4u);
            }
            unsigned bf[4][2];
#pragma unroll
            for (int ntp = 0; ntp < 2; ntp++) {
                int nrow = wn * 32 + ntp * 16 + bRowOff;
                int c2 = ks * 2 + bKhalf;
                unsigned off = (unsigned)(nrow * 32) + (((unsigned)(c2 * 4)) ^ (((unsigned)nrow & 7u) << 2));
                ldsm_x4(bf[2 * ntp][0], bf[2 * ntp][1],
                        bf[2 * ntp + 1][0], bf[2 * ntp + 1][1], stB + off * 4u);
            }
#pragma unroll
            for (int nt = 0; nt < 4; nt++)
#pragma unroll
                for (int mt = 0; mt < MT; mt++)
                    HMMA16816(acc[mt][nt], af[mt][0], af[mt][1], af[mt][2], af[mt][3],
                              bf[nt][0], bf[nt][1]);
        }
        // (no trailing __syncthreads: 3-stage pipeline guarantees safety)
    }

#pragma unroll
    for (int mt = 0; mt < MT; mt++) {
        int row = rowBase + wm * (MT * 16) + mt * 16 + lq;
#pragma unroll
        for (int nt = 0; nt < 4; nt++) {
            int col = colBase + wn * 32 + nt * 8 + lr * 2;
            float b0 = bias[col], b1 = bias[col + 1];
            float v00 = acc[mt][nt][0] + b0;
            float v01 = acc[mt][nt][1] + b1;
            float v10 = acc[mt][nt][2] + b0;
            float v11 = acc[mt][nt][3] + b1;
            if (MODE == 1) {
                v00 = 0.5f * v00 * (1.0f + erff(v00 * 0.70710678118654752f));
                v01 = 0.5f * v01 * (1.0f + erff(v01 * 0.70710678118654752f));
                v10 = 0.5f * v10 * (1.0f + erff(v10 * 0.70710678118654752f));
                v11 = 0.5f * v11 * (1.0f + erff(v11 * 0.70710678118654752f));
            }
            if (MODE == 0 || MODE == 1) {
                __half* C = (__half*)Cv;
                *(unsigned*)(C + (size_t)row * N + col)       = packh2(v00, v01);
                *(unsigned*)(C + (size_t)(row + 8) * N + col) = packh2(v10, v11);
            } else if (MODE == 2) {
                float* C = (float*)Cv;
                float2 c0 = *(const float2*)(C + (size_t)row * N + col);
                float2 c1 = *(const float2*)(C + (size_t)(row + 8) * N + col);
                c0.x += v00; c0.y += v01;
                c1.x += v10; c1.y += v11;
                *(float2*)(C + (size_t)row * N + col) = c0;
                *(float2*)(C + (size_t)(row + 8) * N + col) = c1;
            } else {  // MODE 4: V transposed store -> vt[(b*DMODEL+col)*SEQ + tok]
                __half* C = (__half*)Cv;
                int bb = row >> 9;
                int tok = row & 511;
                size_t base = ((size_t)(bb * DMODEL + col)) * SEQ;
                C[base + tok]           = __float2half_rn(v00);
                C[base + SEQ + tok]     = __float2half_rn(v01);
                C[base + tok + 8]       = __float2half_rn(v10);
                C[base + SEQ + tok + 8] = __float2half_rn(v11);
            }
        }
    }
}

template <int MT, int MODE>
__global__ __launch_bounds__(256) void h_gemm_kernel(
    const __half* __restrict__ A, const __half* __restrict__ BT,
    const float* __restrict__ bias, void* __restrict__ C, int N, int K)
{
    h_gemm_core<MT, MODE>(A, BT, bias, C, N, K);
}

__global__ __launch_bounds__(256) void h_gemm_qkv_kernel(
    const __half* __restrict__ A,
    const __half* __restrict__ WqT, const __half* __restrict__ WkT,
    const __half* __restrict__ WvT,
    const float* __restrict__ bq, const float* __restrict__ bk,
    const float* __restrict__ bv,
    __half* __restrict__ q, __half* __restrict__ k, __half* __restrict__ vt)
{
    if (blockIdx.z == 0)      h_gemm_core<4, 0>(A, WqT, bq, (void*)q,  DMODEL, DMODEL);
    else if (blockIdx.z == 1) h_gemm_core<4, 0>(A, WkT, bk, (void*)k,  DMODEL, DMODEL);
    else                      h_gemm_core<4, 4>(A, WvT, bv, (void*)vt, DMODEL, DMODEL);
}

#define HGEMM_SMEM_128 (NSTAGE * (128*32 + 128*32) * 4)   // 98304
#define HGEMM_SMEM_64  (NSTAGE * (64*32  + 128*32) * 4)   // 73728

// ===================== Flash attention (fp16 mma, online softmax) ===========
// __launch_bounds__(256, 2): cap regs at 128 so 2 CTAs co-reside per SM
// (R12 ncu: 136 regs -> 1 CTA/SM, occ 12.4%). Q fragments re-loaded from smem
// per kt via ldmatrix (frees 16 regs; R10 showed the hoist was time-neutral).
#define FA_SMEM_BYTES ((4096 + 2*2048 + 2*2048) * 4)   // 49152

__global__ __launch_bounds__(256, 2) void fattn_kernel(
    const __half* __restrict__ q, const __half* __restrict__ k,
    const __half* __restrict__ vt, float* __restrict__ x)
{
    extern __shared__ unsigned sm[];
    unsigned* Qs = sm;                 // [128][32]
    const unsigned qsB = smem_u32(Qs);
    const unsigned ksB = qsB + 4096 * 4u;   // [2][64][32]
    const unsigned vsB = qsB + 8192 * 4u;   // [2][64][32]

    const int tid = threadIdx.x;
    const int lane = tid & 31;
    const int wid = tid >> 5;
    const int lq = lane >> 2;
    const int lr = lane & 3;

    const int aRowOff = ((lane >> 3) & 1) * 8 + (lane & 7);
    const int aKhalf  = lane >> 4;
    const int bRowOff = ((lane >> 4) & 1) * 8 + (lane & 7);
    const int bKhalf  = (lane >> 3) & 1;

    const int qt = blockIdx.x;
    const int bh = blockIdx.y;
    const int b = bh / NHEAD, h = bh % NHEAD;

    const __half* qb  = q  + ((size_t)b * SEQ + qt * 128) * DMODEL + h * HDIM;
    const __half* kb  = k  + (size_t)b * SEQ * DMODEL + h * HDIM;
    const __half* vtb = vt + (size_t)bh * HDIM * SEQ;

    auto issueQ = [&]() {
#pragma unroll
        for (int i = 0; i < 4; i++) {
            int fi = tid + i * 256;
            int r = fi >> 3, c8 = fi & 7;
            unsigned u = (unsigned)(c8 * 4) ^ (((unsigned)r & 7u) << 2);
            cpa16(qsB + (r * 32 + u) * 4u, qb + (size_t)r * DMODEL + c8 * 8);
        }
    };
    auto issueK = [&](int kt) {
#pragma unroll
        for (int i = 0; i < 2; i++) {
            int fi = tid + i * 256;
            int r = fi >> 3, c8 = fi & 7;
            unsigned u = (unsigned)(c8 * 4) ^ (((unsigned)r & 7u) << 2);
            cpa16(ksB + ((kt & 1) * 2048 + r * 32 + u) * 4u,
                  kb + (size_t)(kt * 64 + r) * DMODEL + c8 * 8);
        }
    };
    auto issueV = [&](int kt) {
#pragma unroll
        for (int i = 0; i < 2; i++) {
            int fi = tid + i * 256;
            int r = fi >> 3, c8 = fi & 7;
            unsigned u = (unsigned)(c8 * 4) ^ (((unsigned)r & 7u) << 2);
            cpa16(vsB + ((kt & 1) * 2048 + r * 32 + u) * 4u,
                  vtb + (size_t)r * SEQ + kt * 64 + c8 * 8);
        }
    };

    issueQ(); issueK(0); issueV(0); cpa_commit();
    issueK(1); issueV(1); cpa_commit();

    float oacc[8][4];
#pragma unroll
    for (int nt = 0; nt < 8; nt++)
#pragma unroll
        for (int t = 0; t < 4; t++) oacc[nt][t] = 0.f;
    float mRun0 = -1e30f, mRun1 = -1e30f;
    float lRun0 = 0.f, lRun1 = 0.f;

    const int r0 = wid * 16 + lq;
    // Precomputed Q-fragment ldmatrix addresses (per-ks), reused each kt.
    unsigned qAddr[4];
#pragma unroll
    for (int ks = 0; ks < 4; ks++) {
        int r = wid * 16 + aRowOff;
        int c2 = ks * 2 + aKhalf;
        qAddr[ks] = qsB + ((unsigned)(r * 32) +
                    (((unsigned)(c2 * 4)) ^ (((unsigned)r & 7u) << 2))) * 4u;
    }

    for (int kt = 0; kt < 8; kt++) {
        cpa_wait<1>();
        __syncthreads();

        float sacc[8][4];
#pragma unroll
        for (int nt = 0; nt < 8; nt++)
#pragma unroll
            for (int t = 0; t < 4; t++) sacc[nt][t] = 0.f;

        const unsigned stK = ksB + (unsigned)((kt & 1) * 2048) * 4u;
        const unsigned stV = vsB + (unsigned)((kt & 1) * 2048) * 4u;
#pragma unroll
        for (int ks = 0; ks < 4; ks++) {
            unsigned qa0, qa1, qa2, qa3;
            ldsm_x4(qa0, qa1, qa2, qa3, qAddr[ks]);
            unsigned kf[8][2];
#pragma unroll
            for (int ntp = 0; ntp < 4; ntp++) {
                int nrow = ntp * 16 + bRowOff;
                int c2 = ks * 2 + bKhalf;
                unsigned off = (unsigned)(nrow * 32) +
                               (((unsigned)(c2 * 4)) ^ (((unsigned)nrow & 7u) << 2));
                ldsm_x4(kf[2 * ntp][0], kf[2 * ntp][1],
                        kf[2 * ntp + 1][0], kf[2 * ntp + 1][1], stK + off * 4u);
            }
#pragma unroll
            for (int nt = 0; nt < 8; nt++)
                HMMA16816(sacc[nt], qa0, qa1, qa2, qa3, kf[nt][0], kf[nt][1]);
        }

        float m0 = -1e30f, m1 = -1e30f;
#pragma unroll
        for (int nt = 0; nt < 8; nt++) {
            sacc[nt][0] *= 0.125f; sacc[nt][1] *= 0.125f;
            sacc[nt][2] *= 0.125f; sacc[nt][3] *= 0.125f;
            m0 = fmaxf(m0, fmaxf(sacc[nt][0], sacc[nt][1]));
            m1 = fmaxf(m1, fmaxf(sacc[nt][2], sacc[nt][3]));
        }
#pragma unroll
        for (int o = 1; o <= 2; o <<= 1) {
            m0 = fmaxf(m0, __shfl_xor_sync(0xffffffffu, m0, o));
            m1 = fmaxf(m1, __shfl_xor_sync(0xffffffffu, m1, o));
        }
        const float nm0 = fmaxf(mRun0, m0);
        const float nm1 = fmaxf(mRun1, m1);
        const float sc0 = __expf(mRun0 - nm0);
        const float sc1 = __expf(mRun1 - nm1);
        mRun0 = nm0; mRun1 = nm1;

        float lt0 = 0.f, lt1 = 0.f;
#pragma unroll
        for (int nt = 0; nt < 8; nt++) {
            sacc[nt][0] = __expf(sacc[nt][0] - nm0);
            sacc[nt][1] = __expf(sacc[nt][1] - nm0);
            sacc[nt][2] = __expf(sacc[nt][2] - nm1);
            sacc[nt][3] = __expf(sacc[nt][3] - nm1);
            lt0 += sacc[nt][0] + sacc[nt][1];
            lt1 += sacc[nt][2] + sacc[nt][3];
        }
        lRun0 = lRun0 * sc0 + lt0;
        lRun1 = lRun1 * sc1 + lt1;
#pragma unroll
        for (int nt = 0; nt < 8; nt++) {
            oacc[nt][0] *= sc0; oacc[nt][1] *= sc0;
            oacc[nt][2] *= sc1; oacc[nt][3] *= sc1;
        }

#pragma unroll
        for (int kc = 0; kc < 4; kc++) {
            unsigned a0 = packh2(sacc[2 * kc][0],     sacc[2 * kc][1]);
            unsigned a1 = packh2(sacc[2 * kc][2],     sacc[2 * kc][3]);
            unsigned a2 = packh2(sacc[2 * kc + 1][0], sacc[2 * kc + 1][1]);
            unsigned a3 = packh2(sacc[2 * kc + 1][2], sacc[2 * kc + 1][3]);
            unsigned vf[8][2];
#pragma unroll
            for (int ntp = 0; ntp < 4; ntp++) {
                int nrow = ntp * 16 + bRowOff;           // dim rows of V^T tile
                int c2 = kc * 2 + bKhalf;
                unsigned off = (unsigned)(nrow * 32) +
                               (((unsigned)(c2 * 4)) ^ (((unsigned)nrow & 7u) << 2));
                ldsm_x4(vf[2 * ntp][0], vf[2 * ntp][1],
                        vf[2 * ntp + 1][0], vf[2 * ntp + 1][1], stV + off * 4u);
            }
#pragma unroll
            for (int nt = 0; nt < 8; nt++)
                HMMA16816(oacc[nt], a0, a1, a2, a3, vf[nt][0], vf[nt][1]);
        }

        __syncthreads();   // 2-deep buffer: must drain readers before refill
        if (kt + 2 < 8) { issueK(kt + 2); issueV(kt + 2); }
        cpa_commit();
    }

#pragma unroll
    for (int o = 1; o <= 2; o <<= 1) {
        lRun0 += __shfl_xor_sync(0xffffffffu, lRun0, o);
        lRun1 += __shfl_xor_sync(0xffffffffu, lRun1, o);
    }
    const float inv0 = 1.f / lRun0;
    const float inv1 = 1.f / lRun1;

    float* xb = x + ((size_t)b * SEQ + qt * 128) * DMODEL + h * HDIM;
#pragma unroll
    for (int nt = 0; nt < 8; nt++) {
        int col = nt * 8 + lr * 2;
        float2 c0 = *(const float2*)(xb + (size_t)r0 * DMODEL + col);
        float2 c1 = *(const float2*)(xb + (size_t)(r0 + 8) * DMODEL + col);
        c0.x += oacc[nt][0] * inv0; c0.y += oacc[nt][1] * inv0;
        c1.x += oacc[nt][2] * inv1; c1.y += oacc[nt][3] * inv1;
        *(float2*)(xb + (size_t)r0 * DMODEL + col) = c0;
        *(float2*)(xb + (size_t)(r0 + 8) * DMODEL + col) = c1;
    }
}

// ---------------- launch ----------------------------------------------------
extern "C" void kernel_launch(void* const* d_in, const int* in_sizes, int n_in,
                              void* d_out, int out_size)
{
    const float* x_in = (const float*)d_in[0];
    const float* Wq = (const float*)d_in[1];
    const float* bq = (const float*)d_in[2];
    const float* Wk = (const float*)d_in[3];
    const float* bk = (const float*)d_in[4];
    const float* Wv = (const float*)d_in[5];
    const float* bv = (const float*)d_in[6];
    const float* g1 = (const float*)d_in[7];
    const float* be1 = (const float*)d_in[8];
    const float* g2 = (const float*)d_in[9];
    const float* be2 = (const float*)d_in[10];
    const float* W0 = (const float*)d_in[11];
    const float* b0 = (const float*)d_in[12];
    const float* W1 = (const float*)d_in[13];
    const float* b1 = (const float*)d_in[14];

    float* x = (float*)d_out;

    void *p_xln, *p_q, *p_k, *p_vt, *p_h1;
    void *p_wq, *p_wk, *p_wv, *p_w0, *p_w1;
    cudaGetSymbolAddress(&p_xln, g_xln);
    cudaGetSymbolAddress(&p_q, g_q);
    cudaGetSymbolAddress(&p_k, g_k);
    cudaGetSymbolAddress(&p_vt, g_vt);
    cudaGetSymbolAddress(&p_h1, g_h1);
    cudaGetSymbolAddress(&p_wq, g_wqT);
    cudaGetSymbolAddress(&p_wk, g_wkT);
    cudaGetSymbolAddress(&p_wv, g_wvT);
    cudaGetSymbolAddress(&p_w0, g_w0T);
    cudaGetSymbolAddress(&p_w1, g_w1T);
    __half* xln = (__half*)p_xln;
    __half* q = (__half*)p_q;
    __half* k = (__half*)p_k;
    __half* vt = (__half*)p_vt;
    __half* h1 = (__half*)p_h1;
    __half* wqT = (__half*)p_wq;
    __half* wkT = (__half*)p_wk;
    __half* wvT = (__half*)p_wv;
    __half* w0T = (__half*)p_w0;
    __half* w1T = (__half*)p_w1;

    cudaFuncSetAttribute(fattn_kernel, cudaFuncAttributeMaxDynamicSharedMemorySize,
                         FA_SMEM_BYTES);
    cudaFuncSetAttribute(h_gemm_qkv_kernel, cudaFuncAttributeMaxDynamicSharedMemorySize,
                         HGEMM_SMEM_128);
    cudaFuncSetAttribute(h_gemm_kernel<4,1>, cudaFuncAttributeMaxDynamicSharedMemorySize,
                         HGEMM_SMEM_128);
    cudaFuncSetAttribute(h_gemm_kernel<2,2>, cudaFuncAttributeMaxDynamicSharedMemorySize,
                         HGEMM_SMEM_64);

    // one launch: all weight transposes + x copy
    prep_kernel<<<PREP_GRID, dim3(32, 8)>>>(
        x_in, x, Wq, Wk, Wv, W0, W1, wqT, wkT, wvT, w0T, w1T);

    const dim3 gemmQKV(DMODEL / 128, NTOK / 128, 3);  // (6,16,3)
    const dim3 gemmFF1(FFDIM / 128, NTOK / 128);      // (24,16)
    const dim3 gemmFF2(DMODEL / 128, NTOK / 64);      // (6,32)
    const dim3 attnGrid(SEQ / 128, BATCH * NHEAD);    // (4,48)

    for (int blk = 0; blk < NBLOCKS; blk++) {
        ln_kernel<<<NTOK / 8, 256>>>(x, g1, be1, xln);
        h_gemm_qkv_kernel<<<gemmQKV, 256, HGEMM_SMEM_128>>>(
            xln, wqT, wkT, wvT, bq, bk, bv, q, k, vt);
        fattn_kernel<<<attnGrid, 256, FA_SMEM_BYTES>>>(q, k, vt, x);
        ln_kernel<<<NTOK / 8, 256>>>(x, g2, be2, xln);
        h_gemm_kernel<4,1><<<gemmFF1, 256, HGEMM_SMEM_128>>>(
            xln, w0T, b0, (void*)h1, FFDIM, DMODEL);
        h_gemm_kernel<2,2><<<gemmFF2, 256, HGEMM_SMEM_64>>>(
            h1, w1T, b1, (void*)x, DMODEL, FFDIM);
    }
}

// round 15
// speedup vs baseline: 1.0652x; 1.0277x over previous
#include <cuda_runtime.h>
#include <cuda_fp16.h>
#include <math.h>
#include <stdint.h>

// Problem constants
#define BATCH 4
#define SEQ   512
#define DMODEL 768
#define FFDIM 3072
#define NHEAD 12
#define HDIM  64
#define NTOK  (BATCH*SEQ)          // 2048
#define NBLOCKS 12

// ---------------- scratch (device globals; no allocation allowed) -----------
__device__ __half g_xln[NTOK * DMODEL];
__device__ __half g_q  [NTOK * DMODEL];
__device__ __half g_k  [NTOK * DMODEL];
__device__ __half g_vt [NTOK * DMODEL];   // per (b,h): [64 dims][512 tokens]
__device__ __half g_h1 [NTOK * FFDIM];
// fp16, TRANSPOSED weights: wt[n][k] = half(W[k][n])
__device__ __half g_wqT[DMODEL * DMODEL];
__device__ __half g_wkT[DMODEL * DMODEL];
__device__ __half g_wvT[DMODEL * DMODEL];
__device__ __half g_w0T[FFDIM * DMODEL];
__device__ __half g_w1T[DMODEL * FFDIM];

__device__ __forceinline__ void cpa16(unsigned dst, const void* src) {
    asm volatile("cp.async.cg.shared.global [%0], [%1], 16;\n" :: "r"(dst), "l"(src));
}
__device__ __forceinline__ void cpa_commit() {
    asm volatile("cp.async.commit_group;\n" ::: "memory");
}
template <int N>
__device__ __forceinline__ void cpa_wait() {
    asm volatile("cp.async.wait_group %0;\n" :: "n"(N) : "memory");
}
__device__ __forceinline__ unsigned smem_u32(const void* p) {
    unsigned r;
    asm("{ .reg .u64 t; cvta.to.shared.u64 t, %1; cvt.u32.u64 %0, t; }"
        : "=r"(r) : "l"(p));
    return r;
}
__device__ __forceinline__ unsigned packh2(float a, float b) {
    __half2 h = __floats2half2_rn(a, b);
    return *(unsigned*)&h;
}
__device__ __forceinline__ void ldsm_x4(unsigned& r0, unsigned& r1,
                                        unsigned& r2, unsigned& r3, unsigned addr) {
    asm volatile("ldmatrix.sync.aligned.m8n8.x4.shared.b16 {%0,%1,%2,%3}, [%4];"
        : "=r"(r0), "=r"(r1), "=r"(r2), "=r"(r3) : "r"(addr));
}

#define HMMA16816(acc, a0, a1, a2, a3, b0, b1) \
    asm volatile( \
        "mma.sync.aligned.m16n8k16.row.col.f32.f16.f16.f32 " \
        "{%0,%1,%2,%3}, {%4,%5,%6,%7}, {%8,%9}, {%0,%1,%2,%3};" \
        : "+f"((acc)[0]), "+f"((acc)[1]), "+f"((acc)[2]), "+f"((acc)[3]) \
        : "r"(a0), "r"(a1), "r"(a2), "r"(a3), "r"(b0), "r"(b1))

// ---------------- batched prep: 5 weight transposes + x copy, ONE launch ----
__device__ __forceinline__ void transpose_tile(
    const float* __restrict__ src, __half* __restrict__ dst,
    int R, int C, int tileId)
{
    __shared__ float t[32][33];
    const int ctiles = C / 32;
    const int c0 = (tileId % ctiles) * 32;
    const int r0 = (tileId / ctiles) * 32;
    const int tx = threadIdx.x, ty = threadIdx.y;
#pragma unroll
    for (int i = 0; i < 4; i++)
        t[ty + 8 * i][tx] = src[(size_t)(r0 + ty + 8 * i) * C + c0 + tx];
    __syncthreads();
#pragma unroll
    for (int i = 0; i < 4; i++)
        dst[(size_t)(c0 + ty + 8 * i) * R + r0 + tx] = __float2half_rn(t[tx][ty + 8 * i]);
}

__global__ __launch_bounds__(256) void prep_kernel(
    const float* __restrict__ x_in, float* __restrict__ x,
    const float* __restrict__ Wq, const float* __restrict__ Wk,
    const float* __restrict__ Wv, const float* __restrict__ W0,
    const float* __restrict__ W1,
    __half* __restrict__ wqT, __half* __restrict__ wkT, __half* __restrict__ wvT,
    __half* __restrict__ w0T, __half* __restrict__ w1T)
{
    const int bid = blockIdx.x;
    if (bid < 576) {
        transpose_tile(Wq, wqT, DMODEL, DMODEL, bid);
    } else if (bid < 1152) {
        transpose_tile(Wk, wkT, DMODEL, DMODEL, bid - 576);
    } else if (bid < 1728) {
        transpose_tile(Wv, wvT, DMODEL, DMODEL, bid - 1152);
    } else if (bid < 4032) {
        transpose_tile(W0, w0T, DMODEL, FFDIM, bid - 1728);
    } else if (bid < 6336) {
        transpose_tile(W1, w1T, FFDIM, DMODEL, bid - 4032);
    } else {
        const int tid = threadIdx.y * 32 + threadIdx.x;
        const size_t off = (size_t)(bid - 6336) * 1024 + (size_t)tid * 4;
        *(float4*)(x + off) = *(const float4*)(x_in + off);
    }
}
#define PREP_GRID 7872

// ---------------- LayerNorm: warp per row; outputs fp16 ---------------------
__global__ __launch_bounds__(256) void ln_kernel(
    const float* __restrict__ x, const float* __restrict__ g,
    const float* __restrict__ be, __half* __restrict__ y)
{
    const int wid = threadIdx.x >> 5, lane = threadIdx.x & 31;
    const int r = blockIdx.x * 8 + wid;
    const float* xr = x + (size_t)r * DMODEL;

    float4 v[6];
    float s = 0.f, s2 = 0.f;
#pragma unroll
    for (int i = 0; i < 6; i++) {
        v[i] = *(const float4*)(xr + (i * 32 + lane) * 4);
        s  += v[i].x + v[i].y + v[i].z + v[i].w;
        s2 += v[i].x * v[i].x + v[i].y * v[i].y + v[i].z * v[i].z + v[i].w * v[i].w;
    }
#pragma unroll
    for (int o = 16; o > 0; o >>= 1) {
        s  += __shfl_xor_sync(0xffffffffu, s,  o);
        s2 += __shfl_xor_sync(0xffffffffu, s2, o);
    }
    const float mu  = s  * (1.f / DMODEL);
    const float var = s2 * (1.f / DMODEL) - mu * mu;
    const float inv = rsqrtf(var + 1e-5f);
    __half* yr = y + (size_t)r * DMODEL;
#pragma unroll
    for (int i = 0; i < 6; i++) {
        const int col = (i * 32 + lane) * 4;
        float4 gg = *(const float4*)(g + col);
        float4 bb = *(const float4*)(be + col);
        unsigned p0 = packh2((v[i].x - mu) * inv * gg.x + bb.x,
                             (v[i].y - mu) * inv * gg.y + bb.y);
        unsigned p1 = packh2((v[i].z - mu) * inv * gg.z + bb.z,
                             (v[i].w - mu) * inv * gg.w + bb.w);
        uint2 o; o.x = p0; o.y = p1;
        *(uint2*)(yr + col) = o;
    }
}

// ===================== FP16 tensor-core GEMM ================================
#define BKH 64
#define NSTAGE 3

template <int MT, int MODE>
__device__ __forceinline__ void h_gemm_core(
    const __half* __restrict__ A, const __half* __restrict__ BT,
    const float* __restrict__ bias, void* __restrict__ Cv,
    int N, int K)
{
    constexpr int BMv  = MT * 32;
    constexpr int ASTG = BMv * 32;
    constexpr int BSTG = 128 * 32;

    extern __shared__ unsigned smemU[];
    unsigned* As = smemU;
    unsigned* Bs = smemU + NSTAGE * ASTG;
    const unsigned asBase = smem_u32(As);
    const unsigned bsBase = smem_u32(Bs);

    const int tid  = threadIdx.x;
    const int lane = tid & 31;
    const int wid  = tid >> 5;
    const int wm   = wid >> 2;
    const int wn   = wid & 3;
    const int rowBase = blockIdx.y * BMv;
    const int colBase = blockIdx.x * 128;
    const int lq = lane >> 2;
    const int lr = lane & 3;

    const int aRowOff = ((lane >> 3) & 1) * 8 + (lane & 7);
    const int aKhalf  = lane >> 4;
    const int bRowOff = ((lane >> 4) & 1) * 8 + (lane & 7);
    const int bKhalf  = (lane >> 3) & 1;

    auto issue = [&](int c) {
        const int st = c % NSTAGE;
        const int k0 = c * BKH;
#pragma unroll
        for (int i = 0; i < MT; i++) {
            int fi = tid + i * 256;
            int r = fi >> 3, c8 = fi & 7;
            unsigned u = (unsigned)(c8 * 4) ^ (((unsigned)r & 7u) << 2);
            cpa16(asBase + (st * ASTG + r * 32 + u) * 4u,
                  A + (size_t)(rowBase + r) * K + k0 + c8 * 8);
        }
#pragma unroll
        for (int i = 0; i < 4; i++) {
            int fi = tid + i * 256;
            int r = fi >> 3, c8 = fi & 7;
            unsigned u = (unsigned)(c8 * 4) ^ (((unsigned)r & 7u) << 2);
            cpa16(bsBase + (st * BSTG + r * 32 + u) * 4u,
                  BT + (size_t)(colBase + r) * K + k0 + c8 * 8);
        }
    };

    float acc[MT][4][4];
#pragma unroll
    for (int i = 0; i < MT; i++)
#pragma unroll
        for (int j = 0; j < 4; j++)
#pragma unroll
            for (int t = 0; t < 4; t++) acc[i][j][t] = 0.f;

    const int nch = K / BKH;
    issue(0); cpa_commit();
    issue(1); cpa_commit();

    for (int c = 0; c < nch; c++) {
        cpa_wait<1>();
        __syncthreads();
        if (c + 2 < nch) issue(c + 2);
        cpa_commit();

        const unsigned stA = asBase + (unsigned)((c % NSTAGE) * ASTG) * 4u;
        const unsigned stB = bsBase + (unsigned)((c % NSTAGE) * BSTG) * 4u;
#pragma unroll
        for (int ks = 0; ks < 4; ks++) {
            unsigned af[MT][4];
#pragma unroll
            for (int mt = 0; mt < MT; mt++) {
                int r = wm * (MT * 16) + mt * 16 + aRowOff;
                int c2 = ks * 2 + aKhalf;
                unsigned off = (unsigned)(r * 32) + (((unsigned)(c2 * 4)) ^ (((unsigned)r & 7u) << 2));
                ldsm_x4(af[mt][0], af[mt][1], af[mt][2], af[mt][3], stA + off * 4u);
            }
            unsigned bf[4][2];
#pragma unroll
            for (int ntp = 0; ntp < 2; ntp++) {
                int nrow = wn * 32 + ntp * 16 + bRowOff;
                int c2 = ks * 2 + bKhalf;
                unsigned off = (unsigned)(nrow * 32) + (((unsigned)(c2 * 4)) ^ (((unsigned)nrow & 7u) << 2));
                ldsm_x4(bf[2 * ntp][0], bf[2 * ntp][1],
                        bf[2 * ntp + 1][0], bf[2 * ntp + 1][1], stB + off * 4u);
            }
#pragma unroll
            for (int nt = 0; nt < 4; nt++)
#pragma unroll
                for (int mt = 0; mt < MT; mt++)
                    HMMA16816(acc[mt][nt], af[mt][0], af[mt][1], af[mt][2], af[mt][3],
                              bf[nt][0], bf[nt][1]);
        }
        // (no trailing __syncthreads: 3-stage pipeline guarantees safety)
    }

#pragma unroll
    for (int mt = 0; mt < MT; mt++) {
        int row = rowBase + wm * (MT * 16) + mt * 16 + lq;
#pragma unroll
        for (int nt = 0; nt < 4; nt++) {
            int col = colBase + wn * 32 + nt * 8 + lr * 2;
            float b0 = bias[col], b1 = bias[col + 1];
            float v00 = acc[mt][nt][0] + b0;
            float v01 = acc[mt][nt][1] + b1;
            float v10 = acc[mt][nt][2] + b0;
            float v11 = acc[mt][nt][3] + b1;
            if (MODE == 1) {
                v00 = 0.5f * v00 * (1.0f + erff(v00 * 0.70710678118654752f));
                v01 = 0.5f * v01 * (1.0f + erff(v01 * 0.70710678118654752f));
                v10 = 0.5f * v10 * (1.0f + erff(v10 * 0.70710678118654752f));
                v11 = 0.5f * v11 * (1.0f + erff(v11 * 0.70710678118654752f));
            }
            if (MODE == 0 || MODE == 1) {
                __half* C = (__half*)Cv;
                *(unsigned*)(C + (size_t)row * N + col)       = packh2(v00, v01);
                *(unsigned*)(C + (size_t)(row + 8) * N + col) = packh2(v10, v11);
            } else if (MODE == 2) {
                float* C = (float*)Cv;
                float2 c0 = *(const float2*)(C + (size_t)row * N + col);
                float2 c1 = *(const float2*)(C + (size_t)(row + 8) * N + col);
                c0.x += v00; c0.y += v01;
                c1.x += v10; c1.y += v11;
                *(float2*)(C + (size_t)row * N + col) = c0;
                *(float2*)(C + (size_t)(row + 8) * N + col) = c1;
            } else {  // MODE 4: V transposed store -> vt[(b*DMODEL+col)*SEQ + tok]
                __half* C = (__half*)Cv;
                int bb = row >> 9;
                int tok = row & 511;
                size_t base = ((size_t)(bb * DMODEL + col)) * SEQ;
                C[base + tok]           = __float2half_rn(v00);
                C[base + SEQ + tok]     = __float2half_rn(v01);
                C[base + tok + 8]       = __float2half_rn(v10);
                C[base + SEQ + tok + 8] = __float2half_rn(v11);
            }
        }
    }
}

template <int MT, int MODE>
__global__ __launch_bounds__(256) void h_gemm_kernel(
    const __half* __restrict__ A, const __half* __restrict__ BT,
    const float* __restrict__ bias, void* __restrict__ C, int N, int K)
{
    h_gemm_core<MT, MODE>(A, BT, bias, C, N, K);
}

__global__ __launch_bounds__(256) void h_gemm_qkv_kernel(
    const __half* __restrict__ A,
    const __half* __restrict__ WqT, const __half* __restrict__ WkT,
    const __half* __restrict__ WvT,
    const float* __restrict__ bq, const float* __restrict__ bk,
    const float* __restrict__ bv,
    __half* __restrict__ q, __half* __restrict__ k, __half* __restrict__ vt)
{
    if (blockIdx.z == 0)      h_gemm_core<4, 0>(A, WqT, bq, (void*)q,  DMODEL, DMODEL);
    else if (blockIdx.z == 1) h_gemm_core<4, 0>(A, WkT, bk, (void*)k,  DMODEL, DMODEL);
    else                      h_gemm_core<4, 4>(A, WvT, bv, (void*)vt, DMODEL, DMODEL);
}

#define HGEMM_SMEM_128 (NSTAGE * (128*32 + 128*32) * 4)   // 98304
#define HGEMM_SMEM_64  (NSTAGE * (64*32  + 128*32) * 4)   // 73728

// ===================== Flash attention (fp16 mma, online softmax) ===========
// CTA: 64 q-rows x 4 warps (128 threads); grid (8, 48) = 384 CTAs.
// Per-warp work identical to R13 (16 rows x full KV), but 4 CTAs/SM now fit
// the regfile (16K regs/CTA) -> ~3-4x resident warps for latency hiding.
#define FA_SMEM_BYTES ((2048 + 2*2048 + 2*2048) * 4)   // 40960

__global__ __launch_bounds__(128, 4) void fattn_kernel(
    const __half* __restrict__ q, const __half* __restrict__ k,
    const __half* __restrict__ vt, float* __restrict__ x)
{
    extern __shared__ unsigned sm[];
    const unsigned qsB = smem_u32(sm);          // Q [64][32]
    const unsigned ksB = qsB + 2048 * 4u;       // K [2][64][32]
    const unsigned vsB = qsB + 6144 * 4u;       // V [2][64][32]

    const int tid = threadIdx.x;
    const int lane = tid & 31;
    const int wid = tid >> 5;                   // 0..3
    const int lq = lane >> 2;
    const int lr = lane & 3;

    const int aRowOff = ((lane >> 3) & 1) * 8 + (lane & 7);
    const int aKhalf  = lane >> 4;
    const int bRowOff = ((lane >> 4) & 1) * 8 + (lane & 7);
    const int bKhalf  = (lane >> 3) & 1;

    const int qt = blockIdx.x;                  // 0..7 (64-row q tiles)
    const int bh = blockIdx.y;
    const int b = bh / NHEAD, h = bh % NHEAD;

    const __half* qb  = q  + ((size_t)b * SEQ + qt * 64) * DMODEL + h * HDIM;
    const __half* kb  = k  + (size_t)b * SEQ * DMODEL + h * HDIM;
    const __half* vtb = vt + (size_t)bh * HDIM * SEQ;

    auto issueQ = [&]() {
#pragma unroll
        for (int i = 0; i < 4; i++) {
            int fi = tid + i * 128;             // 512 chunks: 64 rows x 8
            int r = fi >> 3, c8 = fi & 7;
            unsigned u = (unsigned)(c8 * 4) ^ (((unsigned)r & 7u) << 2);
            cpa16(qsB + (r * 32 + u) * 4u, qb + (size_t)r * DMODEL + c8 * 8);
        }
    };
    auto issueK = [&](int kt) {
#pragma unroll
        for (int i = 0; i < 4; i++) {
            int fi = tid + i * 128;
            int r = fi >> 3, c8 = fi & 7;
            unsigned u = (unsigned)(c8 * 4) ^ (((unsigned)r & 7u) << 2);
            cpa16(ksB + ((kt & 1) * 2048 + r * 32 + u) * 4u,
                  kb + (size_t)(kt * 64 + r) * DMODEL + c8 * 8);
        }
    };
    auto issueV = [&](int kt) {
#pragma unroll
        for (int i = 0; i < 4; i++) {
            int fi = tid + i * 128;
            int r = fi >> 3, c8 = fi & 7;
            unsigned u = (unsigned)(c8 * 4) ^ (((unsigned)r & 7u) << 2);
            cpa16(vsB + ((kt & 1) * 2048 + r * 32 + u) * 4u,
                  vtb + (size_t)r * SEQ + kt * 64 + c8 * 8);
        }
    };

    issueQ(); issueK(0); issueV(0); cpa_commit();
    issueK(1); issueV(1); cpa_commit();

    float oacc[8][4];
#pragma unroll
    for (int nt = 0; nt < 8; nt++)
#pragma unroll
        for (int t = 0; t < 4; t++) oacc[nt][t] = 0.f;
    float mRun0 = -1e30f, mRun1 = -1e30f;
    float lRun0 = 0.f, lRun1 = 0.f;

    const int r0 = wid * 16 + lq;
    unsigned qAddr[4];
#pragma unroll
    for (int ks = 0; ks < 4; ks++) {
        int r = wid * 16 + aRowOff;
        int c2 = ks * 2 + aKhalf;
        qAddr[ks] = qsB + ((unsigned)(r * 32) +
                    (((unsigned)(c2 * 4)) ^ (((unsigned)r & 7u) << 2))) * 4u;
    }

    for (int kt = 0; kt < 8; kt++) {
        cpa_wait<1>();
        __syncthreads();

        float sacc[8][4];
#pragma unroll
        for (int nt = 0; nt < 8; nt++)
#pragma unroll
            for (int t = 0; t < 4; t++) sacc[nt][t] = 0.f;

        const unsigned stK = ksB + (unsigned)((kt & 1) * 2048) * 4u;
        const unsigned stV = vsB + (unsigned)((kt & 1) * 2048) * 4u;
#pragma unroll
        for (int ks = 0; ks < 4; ks++) {
            unsigned qa0, qa1, qa2, qa3;
            ldsm_x4(qa0, qa1, qa2, qa3, qAddr[ks]);
            unsigned kf[8][2];
#pragma unroll
            for (int ntp = 0; ntp < 4; ntp++) {
                int nrow = ntp * 16 + bRowOff;
                int c2 = ks * 2 + bKhalf;
                unsigned off = (unsigned)(nrow * 32) +
                               (((unsigned)(c2 * 4)) ^ (((unsigned)nrow & 7u) << 2));
                ldsm_x4(kf[2 * ntp][0], kf[2 * ntp][1],
                        kf[2 * ntp + 1][0], kf[2 * ntp + 1][1], stK + off * 4u);
            }
#pragma unroll
            for (int nt = 0; nt < 8; nt++)
                HMMA16816(sacc[nt], qa0, qa1, qa2, qa3, kf[nt][0], kf[nt][1]);
        }

        float m0 = -1e30f, m1 = -1e30f;
#pragma unroll
        for (int nt = 0; nt < 8; nt++) {
            sacc[nt][0] *= 0.125f; sacc[nt][1] *= 0.125f;
            sacc[nt][2] *= 0.125f; sacc[nt][3] *= 0.125f;
            m0 = fmaxf(m0, fmaxf(sacc[nt][0], sacc[nt][1]));
            m1 = fmaxf(m1, fmaxf(sacc[nt][2], sacc[nt][3]));
        }
#pragma unroll
        for (int o = 1; o <= 2; o <<= 1) {
            m0 = fmaxf(m0, __shfl_xor_sync(0xffffffffu, m0, o));
            m1 = fmaxf(m1, __shfl_xor_sync(0xffffffffu, m1, o));
        }
        const float nm0 = fmaxf(mRun0, m0);
        const float nm1 = fmaxf(mRun1, m1);
        const float sc0 = __expf(mRun0 - nm0);
        const float sc1 = __expf(mRun1 - nm1);
        mRun0 = nm0; mRun1 = nm1;

        float lt0 = 0.f, lt1 = 0.f;
#pragma unroll
        for (int nt = 0; nt < 8; nt++) {
            sacc[nt][0] = __expf(sacc[nt][0] - nm0);
            sacc[nt][1] = __expf(sacc[nt][1] - nm0);
            sacc[nt][2] = __expf(sacc[nt][2] - nm1);
            sacc[nt][3] = __expf(sacc[nt][3] - nm1);
            lt0 += sacc[nt][0] + sacc[nt][1];
            lt1 += sacc[nt][2] + sacc[nt][3];
        }
        lRun0 = lRun0 * sc0 + lt0;
        lRun1 = lRun1 * sc1 + lt1;
#pragma unroll
        for (int nt = 0; nt < 8; nt++) {
            oacc[nt][0] *= sc0; oacc[nt][1] *= sc0;
            oacc[nt][2] *= sc1; oacc[nt][3] *= sc1;
        }

#pragma unroll
        for (int kc = 0; kc < 4; kc++) {
            unsigned a0 = packh2(sacc[2 * kc][0],     sacc[2 * kc][1]);
            unsigned a1 = packh2(sacc[2 * kc][2],     sacc[2 * kc][3]);
            unsigned a2 = packh2(sacc[2 * kc + 1][0], sacc[2 * kc + 1][1]);
            unsigned a3 = packh2(sacc[2 * kc + 1][2], sacc[2 * kc + 1][3]);
            unsigned vf[8][2];
#pragma unroll
            for (int ntp = 0; ntp < 4; ntp++) {
                int nrow = ntp * 16 + bRowOff;           // dim rows of V^T tile
                int c2 = kc * 2 + bKhalf;
                unsigned off = (unsigned)(nrow * 32) +
                               (((unsigned)(c2 * 4)) ^ (((unsigned)nrow & 7u) << 2));
                ldsm_x4(vf[2 * ntp][0], vf[2 * ntp][1],
                        vf[2 * ntp + 1][0], vf[2 * ntp + 1][1], stV + off * 4u);
            }
#pragma unroll
            for (int nt = 0; nt < 8; nt++)
                HMMA16816(oacc[nt], a0, a1, a2, a3, vf[nt][0], vf[nt][1]);
        }

        __syncthreads();   // 2-deep buffer: must drain readers before refill
        if (kt + 2 < 8) { issueK(kt + 2); issueV(kt + 2); }
        cpa_commit();
    }

#pragma unroll
    for (int o = 1; o <= 2; o <<= 1) {
        lRun0 += __shfl_xor_sync(0xffffffffu, lRun0, o);
        lRun1 += __shfl_xor_sync(0xffffffffu, lRun1, o);
    }
    const float inv0 = 1.f / lRun0;
    const float inv1 = 1.f / lRun1;

    float* xb = x + ((size_t)b * SEQ + qt * 64) * DMODEL + h * HDIM;
#pragma unroll
    for (int nt = 0; nt < 8; nt++) {
        int col = nt * 8 + lr * 2;
        float2 c0 = *(const float2*)(xb + (size_t)r0 * DMODEL + col);
        float2 c1 = *(const float2*)(xb + (size_t)(r0 + 8) * DMODEL + col);
        c0.x += oacc[nt][0] * inv0; c0.y += oacc[nt][1] * inv0;
        c1.x += oacc[nt][2] * inv1; c1.y += oacc[nt][3] * inv1;
        *(float2*)(xb + (size_t)r0 * DMODEL + col) = c0;
        *(float2*)(xb + (size_t)(r0 + 8) * DMODEL + col) = c1;
    }
}

// ---------------- launch ----------------------------------------------------
extern "C" void kernel_launch(void* const* d_in, const int* in_sizes, int n_in,
                              void* d_out, int out_size)
{
    const float* x_in = (const float*)d_in[0];
    const float* Wq = (const float*)d_in[1];
    const float* bq = (const float*)d_in[2];
    const float* Wk = (const float*)d_in[3];
    const float* bk = (const float*)d_in[4];
    const float* Wv = (const float*)d_in[5];
    const float* bv = (const float*)d_in[6];
    const float* g1 = (const float*)d_in[7];
    const float* be1 = (const float*)d_in[8];
    const float* g2 = (const float*)d_in[9];
    const float* be2 = (const float*)d_in[10];
    const float* W0 = (const float*)d_in[11];
    const float* b0 = (const float*)d_in[12];
    const float* W1 = (const float*)d_in[13];
    const float* b1 = (const float*)d_in[14];

    float* x = (float*)d_out;

    void *p_xln, *p_q, *p_k, *p_vt, *p_h1;
    void *p_wq, *p_wk, *p_wv, *p_w0, *p_w1;
    cudaGetSymbolAddress(&p_xln, g_xln);
    cudaGetSymbolAddress(&p_q, g_q);
    cudaGetSymbolAddress(&p_k, g_k);
    cudaGetSymbolAddress(&p_vt, g_vt);
    cudaGetSymbolAddress(&p_h1, g_h1);
    cudaGetSymbolAddress(&p_wq, g_wqT);
    cudaGetSymbolAddress(&p_wk, g_wkT);
    cudaGetSymbolAddress(&p_wv, g_wvT);
    cudaGetSymbolAddress(&p_w0, g_w0T);
    cudaGetSymbolAddress(&p_w1, g_w1T);
    __half* xln = (__half*)p_xln;
    __half* q = (__half*)p_q;
    __half* k = (__half*)p_k;
    __half* vt = (__half*)p_vt;
    __half* h1 = (__half*)p_h1;
    __half* wqT = (__half*)p_wq;
    __half* wkT = (__half*)p_wk;
    __half* wvT = (__half*)p_wv;
    __half* w0T = (__half*)p_w0;
    __half* w1T = (__half*)p_w1;

    cudaFuncSetAttribute(fattn_kernel, cudaFuncAttributeMaxDynamicSharedMemorySize,
                         FA_SMEM_BYTES);
    cudaFuncSetAttribute(h_gemm_qkv_kernel, cudaFuncAttributeMaxDynamicSharedMemorySize,
                         HGEMM_SMEM_128);
    cudaFuncSetAttribute(h_gemm_kernel<4,1>, cudaFuncAttributeMaxDynamicSharedMemorySize,
                         HGEMM_SMEM_128);
    cudaFuncSetAttribute(h_gemm_kernel<2,2>, cudaFuncAttributeMaxDynamicSharedMemorySize,
                         HGEMM_SMEM_64);

    // one launch: all weight transposes + x copy
    prep_kernel<<<PREP_GRID, dim3(32, 8)>>>(
        x_in, x, Wq, Wk, Wv, W0, W1, wqT, wkT, wvT, w0T, w1T);

    const dim3 gemmQKV(DMODEL / 128, NTOK / 128, 3);  // (6,16,3)
    const dim3 gemmFF1(FFDIM / 128, NTOK / 128);      // (24,16)
    const dim3 gemmFF2(DMODEL / 128, NTOK / 64);      // (6,32)
    const dim3 attnGrid(SEQ / 64, BATCH * NHEAD);     // (8,48)

    for (int blk = 0; blk < NBLOCKS; blk++) {
        ln_kernel<<<NTOK / 8, 256>>>(x, g1, be1, xln);
        h_gemm_qkv_kernel<<<gemmQKV, 256, HGEMM_SMEM_128>>>(
            xln, wqT, wkT, wvT, bq, bk, bv, q, k, vt);
        fattn_kernel<<<attnGrid, 128, FA_SMEM_BYTES>>>(q, k, vt, x);
        ln_kernel<<<NTOK / 8, 256>>>(x, g2, be2, xln);
        h_gemm_kernel<4,1><<<gemmFF1, 256, HGEMM_SMEM_128>>>(
            xln, w0T, b0, (void*)h1, FFDIM, DMODEL);
        h_gemm_kernel<2,2><<<gemmFF2, 256, HGEMM_SMEM_64>>>(
            h1, w1T, b1, (void*)x, DMODEL, FFDIM);
    }
}